// round 7
// baseline (speedup 1.0000x reference)
#include <cuda_runtime.h>
#include <cuda_bf16.h>
#include <math.h>

#define EDIM 512
#define BDIM 4
#define SEQ  2048
#define NH   8
#define DH   64
#define ROWS (BDIM*SEQ)
#define BH   (BDIM*NH)
#define KCAT 1536
#define MAXNORM (1.0f - 4e-3f)

// ---------------- scratch ----------------
__device__ float g_q[ROWS*EDIM];
__device__ float g_k[ROWS*EDIM];
__device__ float g_v[ROWS*EDIM];
__device__ float g_ao[ROWS*EDIM];
__device__ float g_st[ROWS*EDIM];
__device__ __nv_bfloat16 g_xcat[(long)ROWS*KCAT];
__device__ __nv_bfloat16 g_wcat[4L*EDIM*KCAT];
__device__ __nv_bfloat16 g_qh[ROWS*EDIM];
__device__ __nv_bfloat16 g_kh[ROWS*EDIM];
__device__ __nv_bfloat16 g_vh[ROWS*EDIM];
__device__ __nv_bfloat16 g_vl[ROWS*EDIM];
__device__ float g_qn[BH*SEQ];
__device__ float g_kn[BH*SEQ];

// ---------------- mma helpers ----------------
__device__ __forceinline__ void ldmA(unsigned r[4], const __nv_bfloat16* p0, int pitch) {
    int l = threadIdx.x & 31;
    unsigned a = (unsigned)__cvta_generic_to_shared(p0 + (l & 15) * pitch + ((l >> 4) << 3));
    asm volatile("ldmatrix.sync.aligned.m8n8.x4.shared.b16 {%0,%1,%2,%3}, [%4];"
                 : "=r"(r[0]), "=r"(r[1]), "=r"(r[2]), "=r"(r[3]) : "r"(a));
}
// B-frags (2 n-tiles) from row-major [n][k] tile
__device__ __forceinline__ void ldmB2(unsigned r[4], const __nv_bfloat16* p0, int pitch) {
    int l = threadIdx.x & 31;
    unsigned a = (unsigned)__cvta_generic_to_shared(p0 + ((l & 7) + ((l >> 4) << 3)) * pitch + (l & 8));
    asm volatile("ldmatrix.sync.aligned.m8n8.x4.shared.b16 {%0,%1,%2,%3}, [%4];"
                 : "=r"(r[0]), "=r"(r[1]), "=r"(r[2]), "=r"(r[3]) : "r"(a));
}
// B-frags (2 n-tiles) from row-major [k][n] tile via trans (V natural layout)
__device__ __forceinline__ void ldmBt(unsigned r[4], const __nv_bfloat16* p0, int pitch) {
    int l = threadIdx.x & 31;
    unsigned a = (unsigned)__cvta_generic_to_shared(
        p0 + ((l & 7) + ((l >> 3) & 1) * 8) * pitch + ((l >> 4) << 3));
    asm volatile("ldmatrix.sync.aligned.m8n8.x4.trans.shared.b16 {%0,%1,%2,%3}, [%4];"
                 : "=r"(r[0]), "=r"(r[1]), "=r"(r[2]), "=r"(r[3]) : "r"(a));
}
__device__ __forceinline__ void mmabf(float c[4], const unsigned a[4], unsigned b0, unsigned b1) {
    asm volatile("mma.sync.aligned.m16n8k16.row.col.f32.bf16.bf16.f32 "
                 "{%0,%1,%2,%3},{%4,%5,%6,%7},{%8,%9},{%0,%1,%2,%3};"
                 : "+f"(c[0]), "+f"(c[1]), "+f"(c[2]), "+f"(c[3])
                 : "r"(a[0]), "r"(a[1]), "r"(a[2]), "r"(a[3]), "r"(b0), "r"(b1));
}
__device__ __forceinline__ unsigned packbf(float lo, float hi) {
    unsigned r;
    asm("cvt.rn.bf16x2.f32 %0, %1, %2;" : "=r"(r) : "f"(hi), "f"(lo));
    return r;
}
__device__ __forceinline__ void cpa16(void* s, const void* g) {
    unsigned a = (unsigned)__cvta_generic_to_shared(s);
    asm volatile("cp.async.cg.shared.global [%0], [%1], 16;" :: "r"(a), "l"(g));
}

// ---------------- split_cat: fp32 -> bf16 [hi|hi|lo](pat0) / [hi|lo|hi](pat1) ----
__global__ __launch_bounds__(256) void split_cat(const float* __restrict__ src,
                                                 __nv_bfloat16* __restrict__ dst,
                                                 long n2, int pat) {
    long i = (long)blockIdx.x * blockDim.x + threadIdx.x;
    if (i >= n2) return;
    long e = i * 2;
    long r = e >> 9; int c = (int)(e & 511);
    float v0 = src[e], v1 = src[e + 1];
    __nv_bfloat16 h0 = __float2bfloat16_rn(v0), h1 = __float2bfloat16_rn(v1);
    __nv_bfloat16 l0 = __float2bfloat16_rn(v0 - __bfloat162float(h0));
    __nv_bfloat16 l1 = __float2bfloat16_rn(v1 - __bfloat162float(h1));
    __nv_bfloat16* p = dst + r * KCAT + c;
    p[0] = h0; p[1] = h1;
    if (pat == 0) { p[512] = h0; p[513] = h1; p[1024] = l0; p[1025] = l1; }
    else          { p[512] = l0; p[513] = l1; p[1024] = h0; p[1025] = h1; }
}

// ---------------- bf16 NT GEMM: C fp32 = A[M,K] @ B[N,K]^T, 128x128, BK=32 ----
__global__ __launch_bounds__(256) void gemm_bf16(const __nv_bfloat16* __restrict__ A,
                                                 const __nv_bfloat16* __restrict__ B,
                                                 float* __restrict__ C,
                                                 int M, int N, int K) {
    __shared__ __nv_bfloat16 As[128][40];
    __shared__ __nv_bfloat16 Bs[128][40];
    const int tid = threadIdx.x, lane = tid & 31, wid = tid >> 5;
    const int wm = wid & 3, wn = wid >> 2;
    const int bm = blockIdx.y * 128, bn = blockIdx.x * 128;

    float acc[2][8][4] = {};
    for (int kt = 0; kt < K; kt += 32) {
#pragma unroll
        for (int i = 0; i < 2; ++i) {
            int slot = tid + i * 256;
            int row = slot >> 2, ch = (slot & 3) * 8;
            *(uint4*)&As[row][ch] = *(const uint4*)&A[(long)(bm + row) * K + kt + ch];
            *(uint4*)&Bs[row][ch] = *(const uint4*)&B[(long)(bn + row) * K + kt + ch];
        }
        __syncthreads();
#pragma unroll
        for (int c = 0; c < 2; ++c) {
            unsigned a0[4], a1[4];
            ldmA(a0, &As[wm * 32][c * 16], 40);
            ldmA(a1, &As[wm * 32 + 16][c * 16], 40);
#pragma unroll
            for (int np = 0; np < 4; ++np) {
                unsigned b[4];
                ldmB2(b, &Bs[wn * 64 + np * 16][c * 16], 40);
                mmabf(acc[0][2 * np], a0, b[0], b[1]);
                mmabf(acc[0][2 * np + 1], a0, b[2], b[3]);
                mmabf(acc[1][2 * np], a1, b[0], b[1]);
                mmabf(acc[1][2 * np + 1], a1, b[2], b[3]);
            }
        }
        __syncthreads();
    }
#pragma unroll
    for (int mt = 0; mt < 2; ++mt) {
        int r0 = bm + wm * 32 + mt * 16 + (lane >> 2);
#pragma unroll
        for (int nt = 0; nt < 8; ++nt) {
            int cc = bn + wn * 64 + nt * 8 + 2 * (lane & 3);
            *(float2*)&C[(long)r0 * N + cc] = make_float2(acc[mt][nt][0], acc[mt][nt][1]);
            *(float2*)&C[(long)(r0 + 8) * N + cc] = make_float2(acc[mt][nt][2], acc[mt][nt][3]);
        }
    }
}

// ---------------- row-wise Mobius transform (+ optional bf16 hi/lo emit) ----
__device__ __forceinline__ float dot4(float4 a, float4 b) {
    return a.x * b.x + a.y * b.y + a.z * b.z + a.w * b.w;
}
__device__ __forceinline__ float warpSum(float v) {
#pragma unroll
    for (int o = 16; o > 0; o >>= 1) v += __shfl_xor_sync(0xffffffffu, v, o);
    return v;
}
__global__ __launch_bounds__(128) void mobius_rows(const float* __restrict__ x,
                                                   const float* __restrict__ mx,
                                                   const float* __restrict__ bias,
                                                   float* __restrict__ out,
                                                   float* __restrict__ hn,
                                                   __nv_bfloat16* __restrict__ ohi,
                                                   __nv_bfloat16* __restrict__ olo) {
    __shared__ float sa[4], sb[4], sc_[4];
    const int t = threadIdx.x, w = t >> 5, lane = t & 31;
    const long r = blockIdx.x;
    const float4 xv = ((const float4*)(x + r * EDIM))[t];
    const float4 mv = ((const float4*)(mx + r * EDIM))[t];
    const float4 bv = ((const float4*)bias)[t];

    float p1 = warpSum(dot4(xv, xv)), p2 = warpSum(dot4(mv, mv));
    if (lane == 0) { sa[w] = p1; sb[w] = p2; }
    __syncthreads();
    float x2 = sa[0] + sa[1] + sa[2] + sa[3];
    float m2 = sb[0] + sb[1] + sb[2] + sb[3];

    float xn = fmaxf(sqrtf(x2), 1e-15f);
    float mn = fmaxf(sqrtf(m2), 1e-15f);
    float u = fminf(xn, 1.0f - 1e-7f);
    float at = 0.5f * (log1pf(u) - log1pf(-u));
    float tt = tanhf(mn / xn * at);
    float sc = tt / mn;
    float4 res = make_float4(mv.x * sc, mv.y * sc, mv.z * sc, mv.w * sc);
    float rn = fmaxf(tt, 1e-15f);
    float pf = (rn > MAXNORM) ? (MAXNORM / rn) : 1.0f;
    res.x *= pf; res.y *= pf; res.z *= pf; res.w *= pf;

    __syncthreads();
    float q1 = warpSum(dot4(res, res)), q2 = warpSum(dot4(bv, bv)), q3 = warpSum(dot4(res, bv));
    if (lane == 0) { sa[w] = q1; sb[w] = q2; sc_[w] = q3; }
    __syncthreads();
    float x2r = sa[0] + sa[1] + sa[2] + sa[3];
    float y2 = sb[0] + sb[1] + sb[2] + sb[3];
    float xy = sc_[0] + sc_[1] + sc_[2] + sc_[3];
    float ca = 1.0f + 2.0f * xy + y2, cb = 1.0f - x2r;
    float den = fmaxf(1.0f + 2.0f * xy + x2r * y2, 1e-15f);
    float inv = 1.0f / den;
    float4 o = make_float4((ca * res.x + cb * bv.x) * inv, (ca * res.y + cb * bv.y) * inv,
                           (ca * res.z + cb * bv.z) * inv, (ca * res.w + cb * bv.w) * inv);
    __syncthreads();
    float q4 = warpSum(dot4(o, o));
    if (lane == 0) sa[w] = q4;
    __syncthreads();
    float o2 = sa[0] + sa[1] + sa[2] + sa[3];
    float on = fmaxf(sqrtf(o2), 1e-15f);
    float pf2 = (on > MAXNORM) ? (MAXNORM / on) : 1.0f;
    o.x *= pf2; o.y *= pf2; o.z *= pf2; o.w *= pf2;
    ((float4*)(out + r * EDIM))[t] = o;

    if (ohi) {
        float f[4] = {o.x, o.y, o.z, o.w};
        unsigned hpack[2];
        float hval[4];
#pragma unroll
        for (int j = 0; j < 2; ++j) {
            __nv_bfloat16 b0 = __float2bfloat16_rn(f[2 * j]);
            __nv_bfloat16 b1 = __float2bfloat16_rn(f[2 * j + 1]);
            hval[2 * j] = __bfloat162float(b0);
            hval[2 * j + 1] = __bfloat162float(b1);
            hpack[j] = ((unsigned)__bfloat16_as_ushort(b1) << 16) | __bfloat16_as_ushort(b0);
        }
        *(uint2*)(ohi + r * EDIM + t * 4) = make_uint2(hpack[0], hpack[1]);
        if (olo) {
            unsigned lp0 = packbf(f[0] - hval[0], f[1] - hval[1]);
            unsigned lp1 = packbf(f[2] - hval[2], f[3] - hval[3]);
            *(uint2*)(olo + r * EDIM + t * 4) = make_uint2(lp0, lp1);
        }
    }

    if (hn) {
        float h = dot4(o, o);
#pragma unroll
        for (int off = 8; off >= 1; off >>= 1) h += __shfl_xor_sync(0xffffffffu, h, off, 16);
        if ((t & 15) == 0) {
            int b = (int)(r / SEQ), s = (int)(r % SEQ);
            hn[((long)b * NH + (t >> 4)) * SEQ + s] = fminf(h, 1.0f - 1e-5f);
        }
    }
}

// ---------------- flash hyperbolic attention v3 ----------------
// 128q CTA, 256 threads = 4 q-groups(32 rows, Q frags in regs) x 2 k-groups.
// 128-key tiles, cp.async double-buffered. m=0 softmax => k-partials add.
#define AP 72
#define TILEU (128 * AP)                 // bf16 units per tile array
#define BUFU  (3 * TILEU)                // K + Vh + Vl
#define ASMB3 ((TILEU + 2 * BUFU) * 2 + (128 + 256) * 4)
#define SCLAMP (-3.952847e-4f)           // -sqrt(1e-5)/8

__global__ void __launch_bounds__(256, 1) attn3(const __nv_bfloat16* __restrict__ qh,
                                                const __nv_bfloat16* __restrict__ kh,
                                                const __nv_bfloat16* __restrict__ vh,
                                                const __nv_bfloat16* __restrict__ vl,
                                                const float* __restrict__ qn,
                                                const float* __restrict__ kn,
                                                float* __restrict__ o) {
    extern __shared__ __nv_bfloat16 dsm[];
    __nv_bfloat16* Qs = dsm;
    __nv_bfloat16* bufs[2] = { dsm + TILEU, dsm + TILEU + BUFU };
    float* qns = (float*)(dsm + TILEU + 2 * BUFU);
    float* kns = qns + 128;              // [2][128]

    const int tid = threadIdx.x, lane = tid & 31, wid = tid >> 5;
    const int wq = wid & 3, wk = wid >> 2;
    const int bh = blockIdx.y, b = bh >> 3, h = bh & 7;
    const int q0 = blockIdx.x * 128;
    const long qrow0 = (long)b * SEQ + q0;

    // Q tile + row norms
#pragma unroll
    for (int it = 0; it < 4; ++it) {
        int slot = tid + it * 256;
        int r = slot >> 3, c8 = (slot & 7) * 8;
        *(uint4*)&Qs[r * AP + c8] = *(const uint4*)&qh[(qrow0 + r) * EDIM + h * DH + c8];
    }
    if (tid < 128) qns[tid] = qn[(long)bh * SEQ + q0 + tid];

    // prefetch tile 0 into buf0
    {
        const long krow0 = (long)b * SEQ;
#pragma unroll
        for (int it = 0; it < 4; ++it) {
            int slot = tid + it * 256;
            int r = slot >> 3, c8 = (slot & 7) * 8;
            long g = (krow0 + r) * EDIM + h * DH + c8;
            cpa16(&bufs[0][r * AP + c8], kh + g);
            cpa16(&bufs[0][TILEU + r * AP + c8], vh + g);
            cpa16(&bufs[0][2 * TILEU + r * AP + c8], vl + g);
        }
        if (tid < 32) cpa16(&kns[tid * 4], kn + (long)bh * SEQ + tid * 4);
        asm volatile("cp.async.commit_group;");
    }
    __syncthreads();

    // Q fragments in registers (permanent)
    unsigned qf[2][4][4];
#pragma unroll
    for (int mt = 0; mt < 2; ++mt)
#pragma unroll
        for (int cs = 0; cs < 4; ++cs)
            ldmA(qf[mt][cs], Qs + (wq * 32 + mt * 16) * AP + cs * 16, AP);

    float qv[2][2], oqv[2][2];
#pragma unroll
    for (int mt = 0; mt < 2; ++mt) {
        qv[mt][0] = qns[wq * 32 + mt * 16 + (lane >> 2)];
        qv[mt][1] = qns[wq * 32 + mt * 16 + (lane >> 2) + 8];
        oqv[mt][0] = 1.0f - qv[mt][0];
        oqv[mt][1] = 1.0f - qv[mt][1];
    }

    float O[2][8][4] = {};
    float ls[2][2] = {};

    for (int t = 0; t < 16; ++t) {
        int cur = t & 1;
        __syncthreads();     // readers of bufs[1-cur] (iter t-1) done
        if (t + 1 < 16) {
            const long krow0 = (long)b * SEQ + (t + 1) * 128;
            __nv_bfloat16* nb = bufs[1 - cur];
#pragma unroll
            for (int it = 0; it < 4; ++it) {
                int slot = tid + it * 256;
                int r = slot >> 3, c8 = (slot & 7) * 8;
                long g = (krow0 + r) * EDIM + h * DH + c8;
                cpa16(&nb[r * AP + c8], kh + g);
                cpa16(&nb[TILEU + r * AP + c8], vh + g);
                cpa16(&nb[2 * TILEU + r * AP + c8], vl + g);
            }
            if (tid < 32) cpa16(&kns[(1 - cur) * 128 + tid * 4],
                                kn + (long)bh * SEQ + (t + 1) * 128 + tid * 4);
            asm volatile("cp.async.commit_group;");
            asm volatile("cp.async.wait_group 1;");
        } else {
            asm volatile("cp.async.wait_group 0;");
        }
        __syncthreads();     // tile t visible to all

        const __nv_bfloat16* Kt  = bufs[cur] + (long)wk * 64 * AP;
        const __nv_bfloat16* Vht = bufs[cur] + TILEU + (long)wk * 64 * AP;
        const __nv_bfloat16* Vlt = bufs[cur] + 2 * TILEU + (long)wk * 64 * AP;
        const float* knt = kns + cur * 128 + wk * 64;

        // S = Q K^T on this warp's 64-key half
        float c[2][8][4] = {};
#pragma unroll
        for (int cs = 0; cs < 4; ++cs)
#pragma unroll
            for (int np = 0; np < 4; ++np) {
                unsigned bb[4];
                ldmB2(bb, Kt + (np * 16) * AP + cs * 16, AP);
                mmabf(c[0][2 * np], qf[0][cs], bb[0], bb[1]);
                mmabf(c[0][2 * np + 1], qf[0][cs], bb[2], bb[3]);
                mmabf(c[1][2 * np], qf[1][cs], bb[0], bb[1]);
                mmabf(c[1][2 * np + 1], qf[1][cs], bb[2], bb[3]);
            }

        // hyperbolic score -> p = exp(score), accumulate partial row sums
#pragma unroll
        for (int mt = 0; mt < 2; ++mt)
#pragma unroll
            for (int nt = 0; nt < 8; ++nt)
#pragma unroll
                for (int e = 0; e < 4; ++e) {
                    int col = nt * 8 + 2 * (lane & 3) + (e & 1);
                    float kvv = knt[col];
                    float qq = qv[mt][e >> 1], oq = oqv[mt][e >> 1];
                    float t2 = 2.0f * fmaf(-qq, kvv, c[mt][nt][e]);
                    float dn = fmaf(oq, 1.0f - kvv, 1e-5f);
                    float s = t2 * __frsqrt_rn(t2 * dn) * (-0.125f);
                    if (t2 <= 1e-5f * dn) s = SCLAMP;
                    float p = __expf(s);
                    c[mt][nt][e] = p;
                    ls[mt][e >> 1] += p;
                }

        // O += P V (3-term), V frags shared across both m-tiles
#pragma unroll
        for (int s = 0; s < 4; ++s) {
            unsigned AH[2][4], AL[2][4];
#pragma unroll
            for (int mt = 0; mt < 2; ++mt)
#pragma unroll
                for (int half = 0; half < 2; ++half) {
                    int t_ = 2 * s + half;
                    float p0 = c[mt][t_][0], p1 = c[mt][t_][1];
                    float p2 = c[mt][t_][2], p3 = c[mt][t_][3];
                    float h0 = __bfloat162float(__float2bfloat16_rn(p0));
                    float h1 = __bfloat162float(__float2bfloat16_rn(p1));
                    float h2 = __bfloat162float(__float2bfloat16_rn(p2));
                    float h3 = __bfloat162float(__float2bfloat16_rn(p3));
                    AH[mt][2 * half]     = packbf(h0, h1);
                    AH[mt][2 * half + 1] = packbf(h2, h3);
                    AL[mt][2 * half]     = packbf(p0 - h0, p1 - h1);
                    AL[mt][2 * half + 1] = packbf(p2 - h2, p3 - h3);
                }
#pragma unroll
            for (int np = 0; np < 4; ++np) {
                unsigned bh_[4], bl_[4];
                ldmBt(bh_, Vht + (s * 16) * AP + np * 16, AP);
                ldmBt(bl_, Vlt + (s * 16) * AP + np * 16, AP);
#pragma unroll
                for (int mt = 0; mt < 2; ++mt) {
                    mmabf(O[mt][2 * np],     AH[mt], bh_[0], bh_[1]);
                    mmabf(O[mt][2 * np + 1], AH[mt], bh_[2], bh_[3]);
                    mmabf(O[mt][2 * np],     AH[mt], bl_[0], bl_[1]);
                    mmabf(O[mt][2 * np + 1], AH[mt], bl_[2], bl_[3]);
                    mmabf(O[mt][2 * np],     AL[mt], bh_[0], bh_[1]);
                    mmabf(O[mt][2 * np + 1], AL[mt], bh_[2], bh_[3]);
                }
            }
        }
    }

    // cross-k combine (m=0 => plain addition of partials)
    __syncthreads();
    float* stage = (float*)dsm;          // 4*32*68 floats
    float* Lst = stage + 4 * 32 * 68;    // 128 floats
    const int SP = 68;

    float lsr[2][2];
#pragma unroll
    for (int mt = 0; mt < 2; ++mt)
#pragma unroll
        for (int hf = 0; hf < 2; ++hf) {
            float v_ = ls[mt][hf];
            v_ += __shfl_xor_sync(0xffffffffu, v_, 1);
            v_ += __shfl_xor_sync(0xffffffffu, v_, 2);
            lsr[mt][hf] = v_;
        }

    if (wk == 1) {
#pragma unroll
        for (int mt = 0; mt < 2; ++mt) {
            int rl = mt * 16 + (lane >> 2);
#pragma unroll
            for (int nt = 0; nt < 8; ++nt) {
                int cc = nt * 8 + 2 * (lane & 3);
                *(float2*)&stage[(wq * 32 + rl) * SP + cc] =
                    make_float2(O[mt][nt][0], O[mt][nt][1]);
                *(float2*)&stage[(wq * 32 + rl + 8) * SP + cc] =
                    make_float2(O[mt][nt][2], O[mt][nt][3]);
            }
            if ((lane & 3) == 0) {
                Lst[wq * 32 + rl] = lsr[mt][0];
                Lst[wq * 32 + rl + 8] = lsr[mt][1];
            }
        }
    }
    __syncthreads();
    if (wk == 0) {
#pragma unroll
        for (int mt = 0; mt < 2; ++mt) {
            int rl = mt * 16 + (lane >> 2);
            float i0 = 1.0f / (lsr[mt][0] + Lst[wq * 32 + rl]);
            float i1 = 1.0f / (lsr[mt][1] + Lst[wq * 32 + rl + 8]);
            float* ob0 = o + (qrow0 + wq * 32 + rl) * EDIM + h * DH;
            float* ob1 = ob0 + 8L * EDIM;
#pragma unroll
            for (int nt = 0; nt < 8; ++nt) {
                int cc = nt * 8 + 2 * (lane & 3);
                float2 s0 = *(float2*)&stage[(wq * 32 + rl) * SP + cc];
                float2 s1 = *(float2*)&stage[(wq * 32 + rl + 8) * SP + cc];
                *(float2*)(ob0 + cc) = make_float2((O[mt][nt][0] + s0.x) * i0,
                                                   (O[mt][nt][1] + s0.y) * i0);
                *(float2*)(ob1 + cc) = make_float2((O[mt][nt][2] + s1.x) * i1,
                                                   (O[mt][nt][3] + s1.y) * i1);
            }
        }
    }
}

// ---------------- launch ----------------
extern "C" void kernel_launch(void* const* d_in, const int* in_sizes, int n_in,
                              void* d_out, int out_size) {
    const float* x  = (const float*)d_in[0];
    const float* Wq = (const float*)d_in[1];
    const float* bq = (const float*)d_in[2];
    const float* Wk = (const float*)d_in[3];
    const float* bk = (const float*)d_in[4];
    const float* Wv = (const float*)d_in[5];
    const float* bv = (const float*)d_in[6];
    const float* Wo = (const float*)d_in[7];
    const float* bo = (const float*)d_in[8];
    float* out = (float*)d_out;

    float *q, *k, *v, *ao, *st, *qn, *kn;
    __nv_bfloat16 *xcat, *wcat, *qhb, *khb, *vhb, *vlb;
    cudaGetSymbolAddress((void**)&q, g_q);
    cudaGetSymbolAddress((void**)&k, g_k);
    cudaGetSymbolAddress((void**)&v, g_v);
    cudaGetSymbolAddress((void**)&ao, g_ao);
    cudaGetSymbolAddress((void**)&st, g_st);
    cudaGetSymbolAddress((void**)&qn, g_qn);
    cudaGetSymbolAddress((void**)&kn, g_kn);
    cudaGetSymbolAddress((void**)&xcat, g_xcat);
    cudaGetSymbolAddress((void**)&wcat, g_wcat);
    cudaGetSymbolAddress((void**)&qhb, g_qh);
    cudaGetSymbolAddress((void**)&khb, g_kh);
    cudaGetSymbolAddress((void**)&vhb, g_vh);
    cudaGetSymbolAddress((void**)&vlb, g_vl);

    cudaFuncSetAttribute(attn3, cudaFuncAttributeMaxDynamicSharedMemorySize, ASMB3);

    const long n2w = (long)EDIM * EDIM / 2;
    const long n2x = (long)ROWS * EDIM / 2;
    const long WSTR = (long)EDIM * KCAT;
    split_cat<<<(unsigned)((n2w + 255) / 256), 256>>>(Wq, wcat + 0 * WSTR, n2w, 1);
    split_cat<<<(unsigned)((n2w + 255) / 256), 256>>>(Wk, wcat + 1 * WSTR, n2w, 1);
    split_cat<<<(unsigned)((n2w + 255) / 256), 256>>>(Wv, wcat + 2 * WSTR, n2w, 1);
    split_cat<<<(unsigned)((n2w + 255) / 256), 256>>>(Wo, wcat + 3 * WSTR, n2w, 1);
    split_cat<<<(unsigned)((n2x + 255) / 256), 256>>>(x, xcat, n2x, 0);

    dim3 gg(EDIM / 128, ROWS / 128);   // (4, 64)
    gemm_bf16<<<gg, 256>>>(xcat, wcat + 0 * WSTR, q, ROWS, EDIM, KCAT);
    gemm_bf16<<<gg, 256>>>(xcat, wcat + 1 * WSTR, k, ROWS, EDIM, KCAT);
    gemm_bf16<<<gg, 256>>>(xcat, wcat + 2 * WSTR, v, ROWS, EDIM, KCAT);

    mobius_rows<<<ROWS, 128>>>(x, q, bq, q, qn, qhb, nullptr);
    mobius_rows<<<ROWS, 128>>>(x, k, bk, k, kn, khb, nullptr);
    mobius_rows<<<ROWS, 128>>>(x, v, bv, v, nullptr, vhb, vlb);

    dim3 ag(SEQ / 128, BH);            // (16, 32)
    attn3<<<ag, 256, ASMB3>>>(qhb, khb, vhb, vlb, qn, kn, ao);

    split_cat<<<(unsigned)((n2x + 255) / 256), 256>>>(ao, xcat, n2x, 0);
    gemm_bf16<<<gg, 256>>>(xcat, wcat + 3 * WSTR, st, ROWS, EDIM, KCAT);
    mobius_rows<<<ROWS, 128>>>(ao, st, bo, out, nullptr, nullptr, nullptr);
}

// round 8
// speedup vs baseline: 1.1945x; 1.1945x over previous
#include <cuda_runtime.h>
#include <cuda_bf16.h>
#include <math.h>

#define EDIM 512
#define BDIM 4
#define SEQ  2048
#define NH   8
#define DH   64
#define ROWS (BDIM*SEQ)
#define BH   (BDIM*NH)
#define KCAT 1536
#define MAXNORM (1.0f - 4e-3f)

// ---------------- scratch ----------------
__device__ float g_q[ROWS*EDIM];
__device__ float g_k[ROWS*EDIM];
__device__ float g_v[ROWS*EDIM];
__device__ float g_ao[ROWS*EDIM];
__device__ float g_st[ROWS*EDIM];
__device__ __nv_bfloat16 g_xcat[(long)ROWS*KCAT];
__device__ __nv_bfloat16 g_wcat[4L*EDIM*KCAT];
__device__ __nv_bfloat16 g_qh[ROWS*EDIM];
__device__ __nv_bfloat16 g_kh[ROWS*EDIM];
__device__ __nv_bfloat16 g_vh[ROWS*EDIM];
__device__ __nv_bfloat16 g_vl[ROWS*EDIM];
__device__ float g_qn[BH*SEQ];
__device__ float g_kn[BH*SEQ];

// ---------------- mma helpers ----------------
__device__ __forceinline__ void ldmA(unsigned r[4], const __nv_bfloat16* p0, int pitch) {
    int l = threadIdx.x & 31;
    unsigned a = (unsigned)__cvta_generic_to_shared(p0 + (l & 15) * pitch + ((l >> 4) << 3));
    asm volatile("ldmatrix.sync.aligned.m8n8.x4.shared.b16 {%0,%1,%2,%3}, [%4];"
                 : "=r"(r[0]), "=r"(r[1]), "=r"(r[2]), "=r"(r[3]) : "r"(a));
}
// B-frags (2 n-tiles) from row-major [n][k] tile
__device__ __forceinline__ void ldmB2(unsigned r[4], const __nv_bfloat16* p0, int pitch) {
    int l = threadIdx.x & 31;
    unsigned a = (unsigned)__cvta_generic_to_shared(p0 + ((l & 7) + ((l >> 4) << 3)) * pitch + (l & 8));
    asm volatile("ldmatrix.sync.aligned.m8n8.x4.shared.b16 {%0,%1,%2,%3}, [%4];"
                 : "=r"(r[0]), "=r"(r[1]), "=r"(r[2]), "=r"(r[3]) : "r"(a));
}
// B-frags (2 n-tiles) from row-major [k][n] tile via trans (V natural layout)
__device__ __forceinline__ void ldmBt(unsigned r[4], const __nv_bfloat16* p0, int pitch) {
    int l = threadIdx.x & 31;
    unsigned a = (unsigned)__cvta_generic_to_shared(
        p0 + ((l & 7) + ((l >> 3) & 1) * 8) * pitch + ((l >> 4) << 3));
    asm volatile("ldmatrix.sync.aligned.m8n8.x4.trans.shared.b16 {%0,%1,%2,%3}, [%4];"
                 : "=r"(r[0]), "=r"(r[1]), "=r"(r[2]), "=r"(r[3]) : "r"(a));
}
__device__ __forceinline__ void mmabf(float c[4], const unsigned a[4], unsigned b0, unsigned b1) {
    asm volatile("mma.sync.aligned.m16n8k16.row.col.f32.bf16.bf16.f32 "
                 "{%0,%1,%2,%3},{%4,%5,%6,%7},{%8,%9},{%0,%1,%2,%3};"
                 : "+f"(c[0]), "+f"(c[1]), "+f"(c[2]), "+f"(c[3])
                 : "r"(a[0]), "r"(a[1]), "r"(a[2]), "r"(a[3]), "r"(b0), "r"(b1));
}
__device__ __forceinline__ unsigned packbf(float lo, float hi) {
    unsigned r;
    asm("cvt.rn.bf16x2.f32 %0, %1, %2;" : "=r"(r) : "f"(hi), "f"(lo));
    return r;
}
__device__ __forceinline__ void cpa16(void* s, const void* g) {
    unsigned a = (unsigned)__cvta_generic_to_shared(s);
    asm volatile("cp.async.cg.shared.global [%0], [%1], 16;" :: "r"(a), "l"(g));
}

// ---------------- split_cat: fp32 -> bf16 [hi|hi|lo](pat0) / [hi|lo|hi](pat1) ----
__global__ __launch_bounds__(256) void split_cat(const float* __restrict__ src,
                                                 __nv_bfloat16* __restrict__ dst,
                                                 long n2, int pat) {
    long i = (long)blockIdx.x * blockDim.x + threadIdx.x;
    if (i >= n2) return;
    long e = i * 2;
    long r = e >> 9; int c = (int)(e & 511);
    float v0 = src[e], v1 = src[e + 1];
    __nv_bfloat16 h0 = __float2bfloat16_rn(v0), h1 = __float2bfloat16_rn(v1);
    __nv_bfloat16 l0 = __float2bfloat16_rn(v0 - __bfloat162float(h0));
    __nv_bfloat16 l1 = __float2bfloat16_rn(v1 - __bfloat162float(h1));
    __nv_bfloat16* p = dst + r * KCAT + c;
    p[0] = h0; p[1] = h1;
    if (pat == 0) { p[512] = h0; p[513] = h1; p[1024] = l0; p[1025] = l1; }
    else          { p[512] = l0; p[513] = l1; p[1024] = h0; p[1025] = h1; }
}

// ---------------- bf16 NT GEMM: C fp32 = A[M,K] @ B[N,K]^T, 128x128, BK=32 ----
__global__ __launch_bounds__(256) void gemm_bf16(const __nv_bfloat16* __restrict__ A,
                                                 const __nv_bfloat16* __restrict__ B,
                                                 float* __restrict__ C,
                                                 int M, int N, int K) {
    __shared__ __nv_bfloat16 As[128][40];
    __shared__ __nv_bfloat16 Bs[128][40];
    const int tid = threadIdx.x, lane = tid & 31, wid = tid >> 5;
    const int wm = wid & 3, wn = wid >> 2;
    const int bm = blockIdx.y * 128, bn = blockIdx.x * 128;

    float acc[2][8][4] = {};
    for (int kt = 0; kt < K; kt += 32) {
#pragma unroll
        for (int i = 0; i < 2; ++i) {
            int slot = tid + i * 256;
            int row = slot >> 2, ch = (slot & 3) * 8;
            *(uint4*)&As[row][ch] = *(const uint4*)&A[(long)(bm + row) * K + kt + ch];
            *(uint4*)&Bs[row][ch] = *(const uint4*)&B[(long)(bn + row) * K + kt + ch];
        }
        __syncthreads();
#pragma unroll
        for (int c = 0; c < 2; ++c) {
            unsigned a0[4], a1[4];
            ldmA(a0, &As[wm * 32][c * 16], 40);
            ldmA(a1, &As[wm * 32 + 16][c * 16], 40);
#pragma unroll
            for (int np = 0; np < 4; ++np) {
                unsigned b[4];
                ldmB2(b, &Bs[wn * 64 + np * 16][c * 16], 40);
                mmabf(acc[0][2 * np], a0, b[0], b[1]);
                mmabf(acc[0][2 * np + 1], a0, b[2], b[3]);
                mmabf(acc[1][2 * np], a1, b[0], b[1]);
                mmabf(acc[1][2 * np + 1], a1, b[2], b[3]);
            }
        }
        __syncthreads();
    }
#pragma unroll
    for (int mt = 0; mt < 2; ++mt) {
        int r0 = bm + wm * 32 + mt * 16 + (lane >> 2);
#pragma unroll
        for (int nt = 0; nt < 8; ++nt) {
            int cc = bn + wn * 64 + nt * 8 + 2 * (lane & 3);
            *(float2*)&C[(long)r0 * N + cc] = make_float2(acc[mt][nt][0], acc[mt][nt][1]);
            *(float2*)&C[(long)(r0 + 8) * N + cc] = make_float2(acc[mt][nt][2], acc[mt][nt][3]);
        }
    }
}

// ---------------- row-wise Mobius transform (+ optional bf16 hi/lo emit) ----
__device__ __forceinline__ float dot4(float4 a, float4 b) {
    return a.x * b.x + a.y * b.y + a.z * b.z + a.w * b.w;
}
__device__ __forceinline__ float warpSum(float v) {
#pragma unroll
    for (int o = 16; o > 0; o >>= 1) v += __shfl_xor_sync(0xffffffffu, v, o);
    return v;
}
__global__ __launch_bounds__(128) void mobius_rows(const float* __restrict__ x,
                                                   const float* __restrict__ mx,
                                                   const float* __restrict__ bias,
                                                   float* __restrict__ out,
                                                   float* __restrict__ hn,
                                                   __nv_bfloat16* __restrict__ ohi,
                                                   __nv_bfloat16* __restrict__ olo) {
    __shared__ float sa[4], sb[4], sc_[4];
    const int t = threadIdx.x, w = t >> 5, lane = t & 31;
    const long r = blockIdx.x;
    const float4 xv = ((const float4*)(x + r * EDIM))[t];
    const float4 mv = ((const float4*)(mx + r * EDIM))[t];
    const float4 bv = ((const float4*)bias)[t];

    float p1 = warpSum(dot4(xv, xv)), p2 = warpSum(dot4(mv, mv));
    if (lane == 0) { sa[w] = p1; sb[w] = p2; }
    __syncthreads();
    float x2 = sa[0] + sa[1] + sa[2] + sa[3];
    float m2 = sb[0] + sb[1] + sb[2] + sb[3];

    float xn = fmaxf(sqrtf(x2), 1e-15f);
    float mn = fmaxf(sqrtf(m2), 1e-15f);
    float u = fminf(xn, 1.0f - 1e-7f);
    float at = 0.5f * (log1pf(u) - log1pf(-u));
    float tt = tanhf(mn / xn * at);
    float sc = tt / mn;
    float4 res = make_float4(mv.x * sc, mv.y * sc, mv.z * sc, mv.w * sc);
    float rn = fmaxf(tt, 1e-15f);
    float pf = (rn > MAXNORM) ? (MAXNORM / rn) : 1.0f;
    res.x *= pf; res.y *= pf; res.z *= pf; res.w *= pf;

    __syncthreads();
    float q1 = warpSum(dot4(res, res)), q2 = warpSum(dot4(bv, bv)), q3 = warpSum(dot4(res, bv));
    if (lane == 0) { sa[w] = q1; sb[w] = q2; sc_[w] = q3; }
    __syncthreads();
    float x2r = sa[0] + sa[1] + sa[2] + sa[3];
    float y2 = sb[0] + sb[1] + sb[2] + sb[3];
    float xy = sc_[0] + sc_[1] + sc_[2] + sc_[3];
    float ca = 1.0f + 2.0f * xy + y2, cb = 1.0f - x2r;
    float den = fmaxf(1.0f + 2.0f * xy + x2r * y2, 1e-15f);
    float inv = 1.0f / den;
    float4 o = make_float4((ca * res.x + cb * bv.x) * inv, (ca * res.y + cb * bv.y) * inv,
                           (ca * res.z + cb * bv.z) * inv, (ca * res.w + cb * bv.w) * inv);
    __syncthreads();
    float q4 = warpSum(dot4(o, o));
    if (lane == 0) sa[w] = q4;
    __syncthreads();
    float o2 = sa[0] + sa[1] + sa[2] + sa[3];
    float on = fmaxf(sqrtf(o2), 1e-15f);
    float pf2 = (on > MAXNORM) ? (MAXNORM / on) : 1.0f;
    o.x *= pf2; o.y *= pf2; o.z *= pf2; o.w *= pf2;
    ((float4*)(out + r * EDIM))[t] = o;

    if (ohi) {
        float f[4] = {o.x, o.y, o.z, o.w};
        unsigned hpack[2];
        float hval[4];
#pragma unroll
        for (int j = 0; j < 2; ++j) {
            __nv_bfloat16 b0 = __float2bfloat16_rn(f[2 * j]);
            __nv_bfloat16 b1 = __float2bfloat16_rn(f[2 * j + 1]);
            hval[2 * j] = __bfloat162float(b0);
            hval[2 * j + 1] = __bfloat162float(b1);
            hpack[j] = ((unsigned)__bfloat16_as_ushort(b1) << 16) | __bfloat16_as_ushort(b0);
        }
        *(uint2*)(ohi + r * EDIM + t * 4) = make_uint2(hpack[0], hpack[1]);
        if (olo) {
            unsigned lp0 = packbf(f[0] - hval[0], f[1] - hval[1]);
            unsigned lp1 = packbf(f[2] - hval[2], f[3] - hval[3]);
            *(uint2*)(olo + r * EDIM + t * 4) = make_uint2(lp0, lp1);
        }
    }

    if (hn) {
        float h = dot4(o, o);
#pragma unroll
        for (int off = 8; off >= 1; off >>= 1) h += __shfl_xor_sync(0xffffffffu, h, off, 16);
        if ((t & 15) == 0) {
            int b = (int)(r / SEQ), s = (int)(r % SEQ);
            hn[((long)b * NH + (t >> 4)) * SEQ + s] = fminf(h, 1.0f - 1e-5f);
        }
    }
}

// ---------------- flash hyperbolic attention v4 ----------------
// attn2 layout (128q x 64k tiles, 256 threads, 8 warps all on full tile)
// + cp.async double-buffered K/Vh/Vl/kn. 2 CTAs/SM enforced.
#define AP 72
#define KVU (64 * AP)            // one 64x64 bf16 array (+pad)
#define BUF3 (3 * KVU)           // K + Vh + Vl
#define ASMB4 ((128 * AP + 2 * BUF3) * 2 + (128 + 2 * 64) * 4)
#define SCLAMP (-3.952847e-4f)   // -sqrt(1e-5)/8

__global__ void __launch_bounds__(256, 2) attn4(const __nv_bfloat16* __restrict__ qh,
                                                const __nv_bfloat16* __restrict__ kh,
                                                const __nv_bfloat16* __restrict__ vh,
                                                const __nv_bfloat16* __restrict__ vl,
                                                const float* __restrict__ qn,
                                                const float* __restrict__ kn,
                                                float* __restrict__ o) {
    extern __shared__ __nv_bfloat16 dsm[];
    __nv_bfloat16* Qs = dsm;                                  // [128][AP]
    __nv_bfloat16* bufs[2] = { dsm + 128 * AP, dsm + 128 * AP + BUF3 };
    float* qns = (float*)(dsm + 128 * AP + 2 * BUF3);         // 128
    float* kns = qns + 128;                                   // [2][64]

    const int tid = threadIdx.x, lane = tid & 31, w = tid >> 5;
    const int bh = blockIdx.y, b = bh >> 3, h = bh & 7;
    const int q0 = blockIdx.x * 128;
    const long qrow0 = (long)b * SEQ + q0;

    // Q tile + row norms (regular loads; Qs persists all iterations)
#pragma unroll
    for (int it = 0; it < 4; ++it) {
        int slot = tid + it * 256;
        int r = slot >> 3, c8 = (slot & 7) * 8;
        *(uint4*)&Qs[r * AP + c8] = *(const uint4*)&qh[(qrow0 + r) * EDIM + h * DH + c8];
    }
    if (tid < 128) qns[tid] = qn[(long)bh * SEQ + q0 + tid];

    // prefetch tile 0
    {
        const long krow0 = (long)b * SEQ;
#pragma unroll
        for (int it = 0; it < 2; ++it) {
            int slot = tid + it * 256;
            int r = slot >> 3, c8 = (slot & 7) * 8;
            long g = (krow0 + r) * EDIM + h * DH + c8;
            cpa16(&bufs[0][r * AP + c8], kh + g);
            cpa16(&bufs[0][KVU + r * AP + c8], vh + g);
            cpa16(&bufs[0][2 * KVU + r * AP + c8], vl + g);
        }
        if (tid < 16) cpa16(&kns[tid * 4], kn + (long)bh * SEQ + tid * 4);
        asm volatile("cp.async.commit_group;");
    }
    __syncthreads();   // qns/Qs visible

    const float qv0 = qns[w * 16 + (lane >> 2)];
    const float qv1 = qns[w * 16 + (lane >> 2) + 8];
    const float oq0 = 1.0f - qv0, oq1 = 1.0f - qv1;

    float O[8][4] = {};
    float ls0 = 0.0f, ls1 = 0.0f;

    for (int t = 0; t < 32; ++t) {
        const int cur = t & 1;
        if (t + 1 < 32) {
            const long krow0 = (long)b * SEQ + (t + 1) * 64;
            __nv_bfloat16* nb = bufs[1 - cur];
#pragma unroll
            for (int it = 0; it < 2; ++it) {
                int slot = tid + it * 256;
                int r = slot >> 3, c8 = (slot & 7) * 8;
                long g = (krow0 + r) * EDIM + h * DH + c8;
                cpa16(&nb[r * AP + c8], kh + g);
                cpa16(&nb[KVU + r * AP + c8], vh + g);
                cpa16(&nb[2 * KVU + r * AP + c8], vl + g);
            }
            if (tid < 16) cpa16(&kns[(1 - cur) * 64 + tid * 4],
                                kn + (long)bh * SEQ + (t + 1) * 64 + tid * 4);
            asm volatile("cp.async.commit_group;");
            asm volatile("cp.async.wait_group 1;");
        } else {
            asm volatile("cp.async.wait_group 0;");
        }
        __syncthreads();   // tile t visible to all warps

        const __nv_bfloat16* Kt  = bufs[cur];
        const __nv_bfloat16* Vht = bufs[cur] + KVU;
        const __nv_bfloat16* Vlt = bufs[cur] + 2 * KVU;
        const float* knt = kns + cur * 64;

        // S = Q K^T (bf16 single pass, K=64)
        float c[8][4] = {};
#pragma unroll
        for (int cs = 0; cs < 4; ++cs) {
            unsigned a[4];
            ldmA(a, Qs + (w * 16) * AP + cs * 16, AP);
#pragma unroll
            for (int np = 0; np < 4; ++np) {
                unsigned bb[4];
                ldmB2(bb, Kt + (np * 16) * AP + cs * 16, AP);
                mmabf(c[2 * np], a, bb[0], bb[1]);
                mmabf(c[2 * np + 1], a, bb[2], bb[3]);
            }
        }

        // hyperbolic score -> p = exp(score) (m = 0)
#pragma unroll
        for (int nt = 0; nt < 8; ++nt) {
#pragma unroll
            for (int e = 0; e < 4; ++e) {
                int col = nt * 8 + 2 * (lane & 3) + (e & 1);
                float kv = knt[col];
                float qq = (e < 2) ? qv0 : qv1;
                float oq = (e < 2) ? oq0 : oq1;
                float t2 = 2.0f * fmaf(-qq, kv, c[nt][e]);
                float dn = fmaf(oq, 1.0f - kv, 1e-5f);
                float s = t2 * __frsqrt_rn(t2 * dn) * (-0.125f);
                if (t2 <= 1e-5f * dn) s = SCLAMP;
                float p = __expf(s);
                c[nt][e] = p;
                if (e < 2) ls0 += p; else ls1 += p;
            }
        }

        // O += P V  (Ph*Vh + Ph*Vl + Pl*Vh)
#pragma unroll
        for (int s = 0; s < 4; ++s) {
            unsigned AH[4], AL[4];
#pragma unroll
            for (int half = 0; half < 2; ++half) {
                int t_ = 2 * s + half;
                float p0 = c[t_][0], p1 = c[t_][1], p2 = c[t_][2], p3 = c[t_][3];
                float h0 = __bfloat162float(__float2bfloat16_rn(p0));
                float h1 = __bfloat162float(__float2bfloat16_rn(p1));
                float h2 = __bfloat162float(__float2bfloat16_rn(p2));
                float h3 = __bfloat162float(__float2bfloat16_rn(p3));
                AH[2 * half]     = packbf(h0, h1);
                AH[2 * half + 1] = packbf(h2, h3);
                AL[2 * half]     = packbf(p0 - h0, p1 - h1);
                AL[2 * half + 1] = packbf(p2 - h2, p3 - h3);
            }
#pragma unroll
            for (int np = 0; np < 4; ++np) {
                unsigned bh_[4], bl_[4];
                ldmBt(bh_, Vht + (s * 16) * AP + np * 16, AP);
                ldmBt(bl_, Vlt + (s * 16) * AP + np * 16, AP);
                mmabf(O[2 * np],     AH, bh_[0], bh_[1]);
                mmabf(O[2 * np + 1], AH, bh_[2], bh_[3]);
                mmabf(O[2 * np],     AH, bl_[0], bl_[1]);
                mmabf(O[2 * np + 1], AH, bl_[2], bl_[3]);
                mmabf(O[2 * np],     AL, bh_[0], bh_[1]);
                mmabf(O[2 * np + 1], AL, bh_[2], bh_[3]);
            }
        }
        __syncthreads();   // all warps done with bufs[cur] before overwrite
    }

    ls0 += __shfl_xor_sync(0xffffffffu, ls0, 1);
    ls0 += __shfl_xor_sync(0xffffffffu, ls0, 2);
    ls1 += __shfl_xor_sync(0xffffffffu, ls1, 1);
    ls1 += __shfl_xor_sync(0xffffffffu, ls1, 2);
    float il0 = 1.0f / ls0, il1 = 1.0f / ls1;

    int r0 = q0 + w * 16 + (lane >> 2);
    float* ob = o + ((long)b * SEQ + r0) * EDIM + h * DH;
#pragma unroll
    for (int nt = 0; nt < 8; ++nt) {
        int cc = nt * 8 + 2 * (lane & 3);
        *(float2*)(ob + cc) = make_float2(O[nt][0] * il0, O[nt][1] * il0);
        *(float2*)(ob + 8L * EDIM + cc) = make_float2(O[nt][2] * il1, O[nt][3] * il1);
    }
}

// ---------------- launch ----------------
extern "C" void kernel_launch(void* const* d_in, const int* in_sizes, int n_in,
                              void* d_out, int out_size) {
    const float* x  = (const float*)d_in[0];
    const float* Wq = (const float*)d_in[1];
    const float* bq = (const float*)d_in[2];
    const float* Wk = (const float*)d_in[3];
    const float* bk = (const float*)d_in[4];
    const float* Wv = (const float*)d_in[5];
    const float* bv = (const float*)d_in[6];
    const float* Wo = (const float*)d_in[7];
    const float* bo = (const float*)d_in[8];
    float* out = (float*)d_out;

    float *q, *k, *v, *ao, *st, *qn, *kn;
    __nv_bfloat16 *xcat, *wcat, *qhb, *khb, *vhb, *vlb;
    cudaGetSymbolAddress((void**)&q, g_q);
    cudaGetSymbolAddress((void**)&k, g_k);
    cudaGetSymbolAddress((void**)&v, g_v);
    cudaGetSymbolAddress((void**)&ao, g_ao);
    cudaGetSymbolAddress((void**)&st, g_st);
    cudaGetSymbolAddress((void**)&qn, g_qn);
    cudaGetSymbolAddress((void**)&kn, g_kn);
    cudaGetSymbolAddress((void**)&xcat, g_xcat);
    cudaGetSymbolAddress((void**)&wcat, g_wcat);
    cudaGetSymbolAddress((void**)&qhb, g_qh);
    cudaGetSymbolAddress((void**)&khb, g_kh);
    cudaGetSymbolAddress((void**)&vhb, g_vh);
    cudaGetSymbolAddress((void**)&vlb, g_vl);

    cudaFuncSetAttribute(attn4, cudaFuncAttributeMaxDynamicSharedMemorySize, ASMB4);

    const long n2w = (long)EDIM * EDIM / 2;
    const long n2x = (long)ROWS * EDIM / 2;
    const long WSTR = (long)EDIM * KCAT;
    split_cat<<<(unsigned)((n2w + 255) / 256), 256>>>(Wq, wcat + 0 * WSTR, n2w, 1);
    split_cat<<<(unsigned)((n2w + 255) / 256), 256>>>(Wk, wcat + 1 * WSTR, n2w, 1);
    split_cat<<<(unsigned)((n2w + 255) / 256), 256>>>(Wv, wcat + 2 * WSTR, n2w, 1);
    split_cat<<<(unsigned)((n2w + 255) / 256), 256>>>(Wo, wcat + 3 * WSTR, n2w, 1);
    split_cat<<<(unsigned)((n2x + 255) / 256), 256>>>(x, xcat, n2x, 0);

    dim3 gg(EDIM / 128, ROWS / 128);   // (4, 64)
    gemm_bf16<<<gg, 256>>>(xcat, wcat + 0 * WSTR, q, ROWS, EDIM, KCAT);
    gemm_bf16<<<gg, 256>>>(xcat, wcat + 1 * WSTR, k, ROWS, EDIM, KCAT);
    gemm_bf16<<<gg, 256>>>(xcat, wcat + 2 * WSTR, v, ROWS, EDIM, KCAT);

    mobius_rows<<<ROWS, 128>>>(x, q, bq, q, qn, qhb, nullptr);
    mobius_rows<<<ROWS, 128>>>(x, k, bk, k, kn, khb, nullptr);
    mobius_rows<<<ROWS, 128>>>(x, v, bv, v, nullptr, vhb, vlb);

    dim3 ag(SEQ / 128, BH);            // (16, 32)
    attn4<<<ag, 256, ASMB4>>>(qhb, khb, vhb, vlb, qn, kn, ao);

    split_cat<<<(unsigned)((n2x + 255) / 256), 256>>>(ao, xcat, n2x, 0);
    gemm_bf16<<<gg, 256>>>(xcat, wcat + 3 * WSTR, st, ROWS, EDIM, KCAT);
    mobius_rows<<<ROWS, 128>>>(ao, st, bo, out, nullptr, nullptr, nullptr);
}

// round 10
// speedup vs baseline: 1.3100x; 1.0967x over previous
#include <cuda_runtime.h>
#include <cuda_bf16.h>
#include <math.h>

#define EDIM 512
#define BDIM 4
#define SEQ  2048
#define NH   8
#define DH   64
#define ROWS (BDIM*SEQ)
#define BH   (BDIM*NH)
#define KCAT 1536
#define MAXNORM (1.0f - 4e-3f)

// ---------------- scratch ----------------
__device__ float g_qkv[(long)ROWS*3*EDIM];   // fused QKV GEMM output
__device__ float g_st[ROWS*EDIM];
__device__ float g_ao[ROWS*EDIM];
__device__ __nv_bfloat16 g_xcat[(long)ROWS*KCAT];
__device__ __nv_bfloat16 g_wcat[4L*EDIM*KCAT];
__device__ __nv_bfloat16 g_qh[ROWS*EDIM];
__device__ __nv_bfloat16 g_kh[ROWS*EDIM];
__device__ __nv_bfloat16 g_vh[ROWS*EDIM];
__device__ __nv_bfloat16 g_vl[ROWS*EDIM];
__device__ float g_qn[BH*SEQ];
__device__ float g_kn[BH*SEQ];

// ---------------- mma helpers ----------------
__device__ __forceinline__ void ldmA(unsigned r[4], const __nv_bfloat16* p0, int pitch) {
    int l = threadIdx.x & 31;
    unsigned a = (unsigned)__cvta_generic_to_shared(p0 + (l & 15) * pitch + ((l >> 4) << 3));
    asm volatile("ldmatrix.sync.aligned.m8n8.x4.shared.b16 {%0,%1,%2,%3}, [%4];"
                 : "=r"(r[0]), "=r"(r[1]), "=r"(r[2]), "=r"(r[3]) : "r"(a));
}
__device__ __forceinline__ void ldmB2(unsigned r[4], const __nv_bfloat16* p0, int pitch) {
    int l = threadIdx.x & 31;
    unsigned a = (unsigned)__cvta_generic_to_shared(p0 + ((l & 7) + ((l >> 4) << 3)) * pitch + (l & 8));
    asm volatile("ldmatrix.sync.aligned.m8n8.x4.shared.b16 {%0,%1,%2,%3}, [%4];"
                 : "=r"(r[0]), "=r"(r[1]), "=r"(r[2]), "=r"(r[3]) : "r"(a));
}
__device__ __forceinline__ void ldmBt(unsigned r[4], const __nv_bfloat16* p0, int pitch) {
    int l = threadIdx.x & 31;
    unsigned a = (unsigned)__cvta_generic_to_shared(
        p0 + ((l & 7) + ((l >> 3) & 1) * 8) * pitch + ((l >> 4) << 3));
    asm volatile("ldmatrix.sync.aligned.m8n8.x4.trans.shared.b16 {%0,%1,%2,%3}, [%4];"
                 : "=r"(r[0]), "=r"(r[1]), "=r"(r[2]), "=r"(r[3]) : "r"(a));
}
__device__ __forceinline__ void mmabf(float c[4], const unsigned a[4], unsigned b0, unsigned b1) {
    asm volatile("mma.sync.aligned.m16n8k16.row.col.f32.bf16.bf16.f32 "
                 "{%0,%1,%2,%3},{%4,%5,%6,%7},{%8,%9},{%0,%1,%2,%3};"
                 : "+f"(c[0]), "+f"(c[1]), "+f"(c[2]), "+f"(c[3])
                 : "r"(a[0]), "r"(a[1]), "r"(a[2]), "r"(a[3]), "r"(b0), "r"(b1));
}
__device__ __forceinline__ unsigned packbf(float lo, float hi) {
    unsigned r;
    asm("cvt.rn.bf16x2.f32 %0, %1, %2;" : "=r"(r) : "f"(hi), "f"(lo));
    return r;
}
__device__ __forceinline__ void cpa16(void* s, const void* g) {
    unsigned a = (unsigned)__cvta_generic_to_shared(s);
    asm volatile("cp.async.cg.shared.global [%0], [%1], 16;" :: "r"(a), "l"(g));
}
__device__ __forceinline__ float ex2f(float x) {
    float r;
    asm("ex2.approx.f32 %0, %1;" : "=f"(r) : "f"(x));
    return r;
}

// ---------------- split_cat: fp32 -> bf16 [hi|hi|lo](pat0) / [hi|lo|hi](pat1) ----
__global__ __launch_bounds__(256) void split_cat(const float* __restrict__ src,
                                                 __nv_bfloat16* __restrict__ dst,
                                                 long n2, int pat) {
    long i = (long)blockIdx.x * blockDim.x + threadIdx.x;
    if (i >= n2) return;
    long e = i * 2;
    long r = e >> 9; int c = (int)(e & 511);
    float v0 = src[e], v1 = src[e + 1];
    __nv_bfloat16 h0 = __float2bfloat16_rn(v0), h1 = __float2bfloat16_rn(v1);
    __nv_bfloat16 l0 = __float2bfloat16_rn(v0 - __bfloat162float(h0));
    __nv_bfloat16 l1 = __float2bfloat16_rn(v1 - __bfloat162float(h1));
    __nv_bfloat16* p = dst + r * KCAT + c;
    p[0] = h0; p[1] = h1;
    if (pat == 0) { p[512] = h0; p[513] = h1; p[1024] = l0; p[1025] = l1; }
    else          { p[512] = l0; p[513] = l1; p[1024] = h0; p[1025] = h1; }
}

// ---------------- bf16 NT GEMM, cp.async 2-stage: C fp32 = A[M,K] @ B[N,K]^T ----
__global__ __launch_bounds__(256) void gemm_bf16(const __nv_bfloat16* __restrict__ A,
                                                 const __nv_bfloat16* __restrict__ B,
                                                 float* __restrict__ C,
                                                 int M, int N, int K) {
    __shared__ __align__(16) __nv_bfloat16 As[2][128][40];
    __shared__ __align__(16) __nv_bfloat16 Bs[2][128][40];
    const int tid = threadIdx.x, lane = tid & 31, wid = tid >> 5;
    const int wm = wid & 3, wn = wid >> 2;
    const int bm = blockIdx.y * 128, bn = blockIdx.x * 128;

    // stage 0 prefetch: 512 slots of 16B per array (full 128x32 bf16 slab)
#pragma unroll
    for (int i = 0; i < 2; ++i) {
        int slot = tid + i * 256;
        int row = slot >> 2, ch = (slot & 3) * 8;
        cpa16(&As[0][row][ch], &A[(long)(bm + row) * K + ch]);
        cpa16(&Bs[0][row][ch], &B[(long)(bn + row) * K + ch]);
    }
    asm volatile("cp.async.commit_group;");

    const int T = K / 32;
    float acc[2][8][4] = {};
    for (int t = 0; t < T; ++t) {
        const int cur = t & 1;
        if (t + 1 < T) {
            const int kt = (t + 1) * 32;
#pragma unroll
            for (int i = 0; i < 2; ++i) {
                int slot = tid + i * 256;
                int row = slot >> 2, ch = (slot & 3) * 8;
                cpa16(&As[1 - cur][row][ch], &A[(long)(bm + row) * K + kt + ch]);
                cpa16(&Bs[1 - cur][row][ch], &B[(long)(bn + row) * K + kt + ch]);
            }
            asm volatile("cp.async.commit_group;");
            asm volatile("cp.async.wait_group 1;");
        } else {
            asm volatile("cp.async.wait_group 0;");
        }
        __syncthreads();
#pragma unroll
        for (int c = 0; c < 2; ++c) {
            unsigned a0[4], a1[4];
            ldmA(a0, &As[cur][wm * 32][c * 16], 40);
            ldmA(a1, &As[cur][wm * 32 + 16][c * 16], 40);
#pragma unroll
            for (int np = 0; np < 4; ++np) {
                unsigned b[4];
                ldmB2(b, &Bs[cur][wn * 64 + np * 16][c * 16], 40);
                mmabf(acc[0][2 * np], a0, b[0], b[1]);
                mmabf(acc[0][2 * np + 1], a0, b[2], b[3]);
                mmabf(acc[1][2 * np], a1, b[0], b[1]);
                mmabf(acc[1][2 * np + 1], a1, b[2], b[3]);
            }
        }
        __syncthreads();
    }
#pragma unroll
    for (int mt = 0; mt < 2; ++mt) {
        int r0 = bm + wm * 32 + mt * 16 + (lane >> 2);
#pragma unroll
        for (int nt = 0; nt < 8; ++nt) {
            int cc = bn + wn * 64 + nt * 8 + 2 * (lane & 3);
            *(float2*)&C[(long)r0 * N + cc] = make_float2(acc[mt][nt][0], acc[mt][nt][1]);
            *(float2*)&C[(long)(r0 + 8) * N + cc] = make_float2(acc[mt][nt][2], acc[mt][nt][3]);
        }
    }
}

// ---------------- warp-per-row Mobius transform (no barriers) ----------------
__device__ __forceinline__ float dot4(float4 a, float4 b) {
    return a.x * b.x + a.y * b.y + a.z * b.z + a.w * b.w;
}
__device__ __forceinline__ float warpSum(float v) {
#pragma unroll
    for (int o = 16; o > 0; o >>= 1) v += __shfl_xor_sync(0xffffffffu, v, o);
    return v;
}
__global__ __launch_bounds__(128) void mobius_rows(const float* __restrict__ x,
                                                   const float* __restrict__ mx, long mxs,
                                                   const float* __restrict__ bias,
                                                   float* __restrict__ out,
                                                   float* __restrict__ hn,
                                                   __nv_bfloat16* __restrict__ ohi,
                                                   __nv_bfloat16* __restrict__ olo) {
    const int lane = threadIdx.x & 31, w = threadIdx.x >> 5;
    const long r = blockIdx.x * 4 + w;
    const float4* xp = (const float4*)(x + r * EDIM);
    const float4* mp = (const float4*)(mx + r * mxs);
    const float4* bp = (const float4*)bias;

    float4 xv[4], mv[4], bv[4];
#pragma unroll
    for (int j = 0; j < 4; ++j) {
        xv[j] = xp[lane + 32 * j];
        mv[j] = mp[lane + 32 * j];
        bv[j] = bp[lane + 32 * j];
    }
    float x2 = 0.0f, m2 = 0.0f;
#pragma unroll
    for (int j = 0; j < 4; ++j) { x2 += dot4(xv[j], xv[j]); m2 += dot4(mv[j], mv[j]); }
    x2 = warpSum(x2); m2 = warpSum(m2);

    float xn = fmaxf(sqrtf(x2), 1e-15f);
    float mn = fmaxf(sqrtf(m2), 1e-15f);
    float u = fminf(xn, 1.0f - 1e-7f);
    float at = 0.5f * (log1pf(u) - log1pf(-u));
    float tt = tanhf(mn / xn * at);
    float sc = tt / mn;
    float rn = fmaxf(tt, 1e-15f);
    float pf = (rn > MAXNORM) ? (MAXNORM / rn) : 1.0f;
    float spf = sc * pf;

    float4 res[4];
#pragma unroll
    for (int j = 0; j < 4; ++j)
        res[j] = make_float4(mv[j].x * spf, mv[j].y * spf, mv[j].z * spf, mv[j].w * spf);

    float x2r = 0.0f, y2 = 0.0f, xy = 0.0f;
#pragma unroll
    for (int j = 0; j < 4; ++j) {
        x2r += dot4(res[j], res[j]);
        y2 += dot4(bv[j], bv[j]);
        xy += dot4(res[j], bv[j]);
    }
    x2r = warpSum(x2r); y2 = warpSum(y2); xy = warpSum(xy);

    float ca = 1.0f + 2.0f * xy + y2, cb = 1.0f - x2r;
    float den = fmaxf(1.0f + 2.0f * xy + x2r * y2, 1e-15f);
    float inv = 1.0f / den;
    float4 o[4];
    float o2 = 0.0f;
#pragma unroll
    for (int j = 0; j < 4; ++j) {
        o[j] = make_float4((ca * res[j].x + cb * bv[j].x) * inv,
                           (ca * res[j].y + cb * bv[j].y) * inv,
                           (ca * res[j].z + cb * bv[j].z) * inv,
                           (ca * res[j].w + cb * bv[j].w) * inv);
        o2 += dot4(o[j], o[j]);
    }
    o2 = warpSum(o2);
    float on = fmaxf(sqrtf(o2), 1e-15f);
    float pf2 = (on > MAXNORM) ? (MAXNORM / on) : 1.0f;
#pragma unroll
    for (int j = 0; j < 4; ++j) {
        o[j].x *= pf2; o[j].y *= pf2; o[j].z *= pf2; o[j].w *= pf2;
    }

    if (out) {
        float4* op = (float4*)(out + r * EDIM);
#pragma unroll
        for (int j = 0; j < 4; ++j) op[lane + 32 * j] = o[j];
    }

    if (ohi) {
#pragma unroll
        for (int j = 0; j < 4; ++j) {
            float f[4] = {o[j].x, o[j].y, o[j].z, o[j].w};
            unsigned hp[2]; float hv[4];
#pragma unroll
            for (int q2 = 0; q2 < 2; ++q2) {
                __nv_bfloat16 b0 = __float2bfloat16_rn(f[2 * q2]);
                __nv_bfloat16 b1 = __float2bfloat16_rn(f[2 * q2 + 1]);
                hv[2 * q2] = __bfloat162float(b0);
                hv[2 * q2 + 1] = __bfloat162float(b1);
                hp[q2] = ((unsigned)__bfloat16_as_ushort(b1) << 16) | __bfloat16_as_ushort(b0);
            }
            *(uint2*)(ohi + r * EDIM + (lane + 32 * j) * 4) = make_uint2(hp[0], hp[1]);
            if (olo) {
                unsigned lp0 = packbf(f[0] - hv[0], f[1] - hv[1]);
                unsigned lp1 = packbf(f[2] - hv[2], f[3] - hv[3]);
                *(uint2*)(olo + r * EDIM + (lane + 32 * j) * 4) = make_uint2(lp0, lp1);
            }
        }
    }

    if (hn) {
        int bb = (int)(r / SEQ), s = (int)(r % SEQ);
#pragma unroll
        for (int j = 0; j < 4; ++j) {
            float hs = dot4(o[j], o[j]);
#pragma unroll
            for (int off = 8; off >= 1; off >>= 1)
                hs += __shfl_xor_sync(0xffffffffu, hs, off, 16);
            if ((lane & 15) == 0) {
                int head = (lane >> 4) + 2 * j;
                hn[((long)bb * NH + head) * SEQ + s] = fminf(hs, 1.0f - 1e-5f);
            }
        }
    }
}

// ---------------- flash hyperbolic attention (attn4 + ex2-folded constant) ----
#define AP 72
#define KVU (64 * AP)
#define BUF3 (3 * KVU)
#define ASMB4 ((128 * AP + 2 * BUF3) * 2 + (128 + 2 * 64) * 4)
#define SCLAMP2 (-5.702734e-4f)   // -sqrt(1e-5)/8 * log2(e)
#define SC2 (-0.1803368801f)      // -0.125 * log2(e)

__global__ void __launch_bounds__(256, 2) attn4(const __nv_bfloat16* __restrict__ qh,
                                                const __nv_bfloat16* __restrict__ kh,
                                                const __nv_bfloat16* __restrict__ vh,
                                                const __nv_bfloat16* __restrict__ vl,
                                                const float* __restrict__ qn,
                                                const float* __restrict__ kn,
                                                float* __restrict__ o) {
    extern __shared__ __nv_bfloat16 dsm[];
    __nv_bfloat16* Qs = dsm;
    __nv_bfloat16* bufs[2] = { dsm + 128 * AP, dsm + 128 * AP + BUF3 };
    float* qns = (float*)(dsm + 128 * AP + 2 * BUF3);
    float* kns = qns + 128;

    const int tid = threadIdx.x, lane = tid & 31, w = tid >> 5;
    const int bh = blockIdx.y, b = bh >> 3, h = bh & 7;
    const int q0 = blockIdx.x * 128;
    const long qrow0 = (long)b * SEQ + q0;

#pragma unroll
    for (int it = 0; it < 4; ++it) {
        int slot = tid + it * 256;
        int r = slot >> 3, c8 = (slot & 7) * 8;
        *(uint4*)&Qs[r * AP + c8] = *(const uint4*)&qh[(qrow0 + r) * EDIM + h * DH + c8];
    }
    if (tid < 128) qns[tid] = qn[(long)bh * SEQ + q0 + tid];

    {
        const long krow0 = (long)b * SEQ;
#pragma unroll
        for (int it = 0; it < 2; ++it) {
            int slot = tid + it * 256;
            int r = slot >> 3, c8 = (slot & 7) * 8;
            long g = (krow0 + r) * EDIM + h * DH + c8;
            cpa16(&bufs[0][r * AP + c8], kh + g);
            cpa16(&bufs[0][KVU + r * AP + c8], vh + g);
            cpa16(&bufs[0][2 * KVU + r * AP + c8], vl + g);
        }
        if (tid < 16) cpa16(&kns[tid * 4], kn + (long)bh * SEQ + tid * 4);
        asm volatile("cp.async.commit_group;");
    }
    __syncthreads();

    const float qv0 = qns[w * 16 + (lane >> 2)];
    const float qv1 = qns[w * 16 + (lane >> 2) + 8];
    const float oq0 = 1.0f - qv0, oq1 = 1.0f - qv1;

    float O[8][4] = {};
    float ls0 = 0.0f, ls1 = 0.0f;

    for (int t = 0; t < 32; ++t) {
        const int cur = t & 1;
        if (t + 1 < 32) {
            const long krow0 = (long)b * SEQ + (t + 1) * 64;
            __nv_bfloat16* nb = bufs[1 - cur];
#pragma unroll
            for (int it = 0; it < 2; ++it) {
                int slot = tid + it * 256;
                int r = slot >> 3, c8 = (slot & 7) * 8;
                long g = (krow0 + r) * EDIM + h * DH + c8;
                cpa16(&nb[r * AP + c8], kh + g);
                cpa16(&nb[KVU + r * AP + c8], vh + g);
                cpa16(&nb[2 * KVU + r * AP + c8], vl + g);
            }
            if (tid < 16) cpa16(&kns[(1 - cur) * 64 + tid * 4],
                                kn + (long)bh * SEQ + (t + 1) * 64 + tid * 4);
            asm volatile("cp.async.commit_group;");
            asm volatile("cp.async.wait_group 1;");
        } else {
            asm volatile("cp.async.wait_group 0;");
        }
        __syncthreads();

        const __nv_bfloat16* Kt  = bufs[cur];
        const __nv_bfloat16* Vht = bufs[cur] + KVU;
        const __nv_bfloat16* Vlt = bufs[cur] + 2 * KVU;
        const float* knt = kns + cur * 64;

        float c[8][4] = {};
#pragma unroll
        for (int cs = 0; cs < 4; ++cs) {
            unsigned a[4];
            ldmA(a, Qs + (w * 16) * AP + cs * 16, AP);
#pragma unroll
            for (int np = 0; np < 4; ++np) {
                unsigned bb[4];
                ldmB2(bb, Kt + (np * 16) * AP + cs * 16, AP);
                mmabf(c[2 * np], a, bb[0], bb[1]);
                mmabf(c[2 * np + 1], a, bb[2], bb[3]);
            }
        }

#pragma unroll
        for (int nt = 0; nt < 8; ++nt) {
#pragma unroll
            for (int e = 0; e < 4; ++e) {
                int col = nt * 8 + 2 * (lane & 3) + (e & 1);
                float kv = knt[col];
                float qq = (e < 2) ? qv0 : qv1;
                float oq = (e < 2) ? oq0 : oq1;
                float t2 = 2.0f * fmaf(-qq, kv, c[nt][e]);
                float dn = fmaf(oq, 1.0f - kv, 1e-5f);
                float s = t2 * __frsqrt_rn(t2 * dn) * SC2;
                if (t2 <= 1e-5f * dn) s = SCLAMP2;
                float p = ex2f(s);
                c[nt][e] = p;
                if (e < 2) ls0 += p; else ls1 += p;
            }
        }

#pragma unroll
        for (int s = 0; s < 4; ++s) {
            unsigned AH[4], AL[4];
#pragma unroll
            for (int half = 0; half < 2; ++half) {
                int t_ = 2 * s + half;
                float p0 = c[t_][0], p1 = c[t_][1], p2 = c[t_][2], p3 = c[t_][3];
                float h0 = __bfloat162float(__float2bfloat16_rn(p0));
                float h1 = __bfloat162float(__float2bfloat16_rn(p1));
                float h2 = __bfloat162float(__float2bfloat16_rn(p2));
                float h3 = __bfloat162float(__float2bfloat16_rn(p3));
                AH[2 * half]     = packbf(h0, h1);
                AH[2 * half + 1] = packbf(h2, h3);
                AL[2 * half]     = packbf(p0 - h0, p1 - h1);
                AL[2 * half + 1] = packbf(p2 - h2, p3 - h3);
            }
#pragma unroll
            for (int np = 0; np < 4; ++np) {
                unsigned bh_[4], bl_[4];
                ldmBt(bh_, Vht + (s * 16) * AP + np * 16, AP);
                ldmBt(bl_, Vlt + (s * 16) * AP + np * 16, AP);
                mmabf(O[2 * np],     AH, bh_[0], bh_[1]);
                mmabf(O[2 * np + 1], AH, bh_[2], bh_[3]);
                mmabf(O[2 * np],     AH, bl_[0], bl_[1]);
                mmabf(O[2 * np + 1], AH, bl_[2], bl_[3]);
                mmabf(O[2 * np],     AL, bh_[0], bh_[1]);
                mmabf(O[2 * np + 1], AL, bh_[2], bh_[3]);
            }
        }
        __syncthreads();
    }

    ls0 += __shfl_xor_sync(0xffffffffu, ls0, 1);
    ls0 += __shfl_xor_sync(0xffffffffu, ls0, 2);
    ls1 += __shfl_xor_sync(0xffffffffu, ls1, 1);
    ls1 += __shfl_xor_sync(0xffffffffu, ls1, 2);
    float il0 = 1.0f / ls0, il1 = 1.0f / ls1;

    int r0 = q0 + w * 16 + (lane >> 2);
    float* ob = o + ((long)b * SEQ + r0) * EDIM + h * DH;
#pragma unroll
    for (int nt = 0; nt < 8; ++nt) {
        int cc = nt * 8 + 2 * (lane & 3);
        *(float2*)(ob + cc) = make_float2(O[nt][0] * il0, O[nt][1] * il0);
        *(float2*)(ob + 8L * EDIM + cc) = make_float2(O[nt][2] * il1, O[nt][3] * il1);
    }
}

// ---------------- launch ----------------
extern "C" void kernel_launch(void* const* d_in, const int* in_sizes, int n_in,
                              void* d_out, int out_size) {
    const float* x  = (const float*)d_in[0];
    const float* Wq = (const float*)d_in[1];
    const float* bq = (const float*)d_in[2];
    const float* Wk = (const float*)d_in[3];
    const float* bk = (const float*)d_in[4];
    const float* Wv = (const float*)d_in[5];
    const float* bv = (const float*)d_in[6];
    const float* Wo = (const float*)d_in[7];
    const float* bo = (const float*)d_in[8];
    float* out = (float*)d_out;

    float *qkv, *st, *ao, *qn, *kn;
    __nv_bfloat16 *xcat, *wcat, *qhb, *khb, *vhb, *vlb;
    cudaGetSymbolAddress((void**)&qkv, g_qkv);
    cudaGetSymbolAddress((void**)&st, g_st);
    cudaGetSymbolAddress((void**)&ao, g_ao);
    cudaGetSymbolAddress((void**)&qn, g_qn);
    cudaGetSymbolAddress((void**)&kn, g_kn);
    cudaGetSymbolAddress((void**)&xcat, g_xcat);
    cudaGetSymbolAddress((void**)&wcat, g_wcat);
    cudaGetSymbolAddress((void**)&qhb, g_qh);
    cudaGetSymbolAddress((void**)&khb, g_kh);
    cudaGetSymbolAddress((void**)&vhb, g_vh);
    cudaGetSymbolAddress((void**)&vlb, g_vl);

    cudaFuncSetAttribute(attn4, cudaFuncAttributeMaxDynamicSharedMemorySize, ASMB4);

    const long n2w = (long)EDIM * EDIM / 2;
    const long n2x = (long)ROWS * EDIM / 2;
    const long WSTR = (long)EDIM * KCAT;
    split_cat<<<(unsigned)((n2w + 255) / 256), 256>>>(Wq, wcat + 0 * WSTR, n2w, 1);
    split_cat<<<(unsigned)((n2w + 255) / 256), 256>>>(Wk, wcat + 1 * WSTR, n2w, 1);
    split_cat<<<(unsigned)((n2w + 255) / 256), 256>>>(Wv, wcat + 2 * WSTR, n2w, 1);
    split_cat<<<(unsigned)((n2w + 255) / 256), 256>>>(Wo, wcat + 3 * WSTR, n2w, 1);
    split_cat<<<(unsigned)((n2x + 255) / 256), 256>>>(x, xcat, n2x, 0);

    // fused QKV GEMM: B rows 0..1535 = [Wq; Wk; Wv] (wcat blocks are contiguous)
    dim3 gq(3 * EDIM / 128, ROWS / 128);   // (12, 64)
    gemm_bf16<<<gq, 256>>>(xcat, wcat, qkv, ROWS, 3 * EDIM, KCAT);

    mobius_rows<<<ROWS / 4, 128>>>(x, qkv + 0 * EDIM, 3 * EDIM, bq, nullptr, qn, qhb, nullptr);
    mobius_rows<<<ROWS / 4, 128>>>(x, qkv + 1 * EDIM, 3 * EDIM, bk, nullptr, kn, khb, nullptr);
    mobius_rows<<<ROWS / 4, 128>>>(x, qkv + 2 * EDIM, 3 * EDIM, bv, nullptr, nullptr, vhb, vlb);

    dim3 ag(SEQ / 128, BH);                // (16, 32)
    attn4<<<ag, 256, ASMB4>>>(qhb, khb, vhb, vlb, qn, kn, ao);

    split_cat<<<(unsigned)((n2x + 255) / 256), 256>>>(ao, xcat, n2x, 0);
    dim3 go(EDIM / 128, ROWS / 128);       // (4, 64)
    gemm_bf16<<<go, 256>>>(xcat, wcat + 3 * WSTR, st, ROWS, EDIM, KCAT);
    mobius_rows<<<ROWS / 4, 128>>>(ao, st, EDIM, bo, out, nullptr, nullptr, nullptr);
}

// round 13
// speedup vs baseline: 1.5074x; 1.1507x over previous
#include <cuda_runtime.h>
#include <cuda_bf16.h>
#include <cuda_fp16.h>
#include <math.h>

#define EDIM 512
#define BDIM 4
#define SEQ  2048
#define NH   8
#define DH   64
#define ROWS (BDIM*SEQ)
#define BH   (BDIM*NH)
#define KCAT 1536
#define MAXNORM (1.0f - 4e-3f)

// ---------------- scratch ----------------
__device__ float g_qkv[(long)ROWS*3*EDIM];   // fused QKV GEMM output
__device__ float g_st[ROWS*EDIM];
__device__ float g_ao[ROWS*EDIM];
__device__ __nv_bfloat16 g_xcat[(long)ROWS*KCAT];
__device__ __nv_bfloat16 g_wcat[4L*EDIM*KCAT];
__device__ __half g_qh[ROWS*EDIM];
__device__ __half g_kh[ROWS*EDIM];
__device__ __half g_vh[ROWS*EDIM];
__device__ float g_qn[BH*SEQ];
__device__ float g_kn[BH*SEQ];

// ---------------- mma helpers ----------------
__device__ __forceinline__ void ldmA(unsigned r[4], const void* p0v, int pitch) {
    const __nv_bfloat16* p0 = (const __nv_bfloat16*)p0v;
    int l = threadIdx.x & 31;
    unsigned a = (unsigned)__cvta_generic_to_shared(p0 + (l & 15) * pitch + ((l >> 4) << 3));
    asm volatile("ldmatrix.sync.aligned.m8n8.x4.shared.b16 {%0,%1,%2,%3}, [%4];"
                 : "=r"(r[0]), "=r"(r[1]), "=r"(r[2]), "=r"(r[3]) : "r"(a));
}
__device__ __forceinline__ void ldmB2(unsigned r[4], const void* p0v, int pitch) {
    const __nv_bfloat16* p0 = (const __nv_bfloat16*)p0v;
    int l = threadIdx.x & 31;
    unsigned a = (unsigned)__cvta_generic_to_shared(p0 + ((l & 7) + ((l >> 4) << 3)) * pitch + (l & 8));
    asm volatile("ldmatrix.sync.aligned.m8n8.x4.shared.b16 {%0,%1,%2,%3}, [%4];"
                 : "=r"(r[0]), "=r"(r[1]), "=r"(r[2]), "=r"(r[3]) : "r"(a));
}
__device__ __forceinline__ void ldmBt(unsigned r[4], const void* p0v, int pitch) {
    const __nv_bfloat16* p0 = (const __nv_bfloat16*)p0v;
    int l = threadIdx.x & 31;
    unsigned a = (unsigned)__cvta_generic_to_shared(
        p0 + ((l & 7) + ((l >> 3) & 1) * 8) * pitch + ((l >> 4) << 3));
    asm volatile("ldmatrix.sync.aligned.m8n8.x4.trans.shared.b16 {%0,%1,%2,%3}, [%4];"
                 : "=r"(r[0]), "=r"(r[1]), "=r"(r[2]), "=r"(r[3]) : "r"(a));
}
__device__ __forceinline__ void mmabf(float c[4], const unsigned a[4], unsigned b0, unsigned b1) {
    asm volatile("mma.sync.aligned.m16n8k16.row.col.f32.bf16.bf16.f32 "
                 "{%0,%1,%2,%3},{%4,%5,%6,%7},{%8,%9},{%0,%1,%2,%3};"
                 : "+f"(c[0]), "+f"(c[1]), "+f"(c[2]), "+f"(c[3])
                 : "r"(a[0]), "r"(a[1]), "r"(a[2]), "r"(a[3]), "r"(b0), "r"(b1));
}
__device__ __forceinline__ void mmaf16(float c[4], const unsigned a[4], unsigned b0, unsigned b1) {
    asm volatile("mma.sync.aligned.m16n8k16.row.col.f32.f16.f16.f32 "
                 "{%0,%1,%2,%3},{%4,%5,%6,%7},{%8,%9},{%0,%1,%2,%3};"
                 : "+f"(c[0]), "+f"(c[1]), "+f"(c[2]), "+f"(c[3])
                 : "r"(a[0]), "r"(a[1]), "r"(a[2]), "r"(a[3]), "r"(b0), "r"(b1));
}
__device__ __forceinline__ unsigned packh2(float lo, float hi) {
    __half2 h = __floats2half2_rn(lo, hi);
    return *(unsigned*)&h;
}
__device__ __forceinline__ void cpa16(void* s, const void* g) {
    unsigned a = (unsigned)__cvta_generic_to_shared(s);
    asm volatile("cp.async.cg.shared.global [%0], [%1], 16;" :: "r"(a), "l"(g));
}
__device__ __forceinline__ float ex2f(float x) {
    float r;
    asm("ex2.approx.f32 %0, %1;" : "=f"(r) : "f"(x));
    return r;
}

// ---------------- split_cat: fp32 -> bf16 [hi|hi|lo](pat0) / [hi|lo|hi](pat1) ----
__device__ __forceinline__ void split_store(const float* __restrict__ src,
                                            __nv_bfloat16* __restrict__ dst,
                                            long i, int pat) {
    long e = i * 2;
    long r = e >> 9; int c = (int)(e & 511);
    float v0 = src[e], v1 = src[e + 1];
    __nv_bfloat16 h0 = __float2bfloat16_rn(v0), h1 = __float2bfloat16_rn(v1);
    __nv_bfloat16 l0 = __float2bfloat16_rn(v0 - __bfloat162float(h0));
    __nv_bfloat16 l1 = __float2bfloat16_rn(v1 - __bfloat162float(h1));
    __nv_bfloat16* p = dst + r * KCAT + c;
    p[0] = h0; p[1] = h1;
    if (pat == 0) { p[512] = h0; p[513] = h1; p[1024] = l0; p[1025] = l1; }
    else          { p[512] = l0; p[513] = l1; p[1024] = h0; p[1025] = h1; }
}
__global__ __launch_bounds__(256) void split_cat(const float* __restrict__ src,
                                                 __nv_bfloat16* __restrict__ dst,
                                                 long n2, int pat) {
    long i = (long)blockIdx.x * blockDim.x + threadIdx.x;
    if (i >= n2) return;
    split_store(src, dst, i, pat);
}
__global__ __launch_bounds__(256) void split_cat_w(const float* __restrict__ w0,
                                                   const float* __restrict__ w1,
                                                   const float* __restrict__ w2,
                                                   const float* __restrict__ w3,
                                                   __nv_bfloat16* __restrict__ dst,
                                                   long n2) {
    long i = (long)blockIdx.x * blockDim.x + threadIdx.x;
    if (i >= n2) return;
    const float* srcs[4] = {w0, w1, w2, w3};
    split_store(srcs[blockIdx.y], dst + (long)blockIdx.y * EDIM * KCAT, i, 1);
}

// ---------------- bf16 NT GEMM, cp.async 2-stage: C fp32 = A[M,K] @ B[N,K]^T ----
__global__ __launch_bounds__(256) void gemm_bf16(const __nv_bfloat16* __restrict__ A,
                                                 const __nv_bfloat16* __restrict__ B,
                                                 float* __restrict__ C,
                                                 int M, int N, int K) {
    __shared__ __align__(16) __nv_bfloat16 As[2][128][40];
    __shared__ __align__(16) __nv_bfloat16 Bs[2][128][40];
    const int tid = threadIdx.x, lane = tid & 31, wid = tid >> 5;
    const int wm = wid & 3, wn = wid >> 2;
    const int bm = blockIdx.y * 128, bn = blockIdx.x * 128;

#pragma unroll
    for (int i = 0; i < 2; ++i) {
        int slot = tid + i * 256;
        int row = slot >> 2, ch = (slot & 3) * 8;
        cpa16(&As[0][row][ch], &A[(long)(bm + row) * K + ch]);
        cpa16(&Bs[0][row][ch], &B[(long)(bn + row) * K + ch]);
    }
    asm volatile("cp.async.commit_group;");

    const int T = K / 32;
    float acc[2][8][4] = {};
    for (int t = 0; t < T; ++t) {
        const int cur = t & 1;
        if (t + 1 < T) {
            const int kt = (t + 1) * 32;
#pragma unroll
            for (int i = 0; i < 2; ++i) {
                int slot = tid + i * 256;
                int row = slot >> 2, ch = (slot & 3) * 8;
                cpa16(&As[1 - cur][row][ch], &A[(long)(bm + row) * K + kt + ch]);
                cpa16(&Bs[1 - cur][row][ch], &B[(long)(bn + row) * K + kt + ch]);
            }
            asm volatile("cp.async.commit_group;");
            asm volatile("cp.async.wait_group 1;");
        } else {
            asm volatile("cp.async.wait_group 0;");
        }
        __syncthreads();
#pragma unroll
        for (int c = 0; c < 2; ++c) {
            unsigned a0[4], a1[4];
            ldmA(a0, &As[cur][wm * 32][c * 16], 40);
            ldmA(a1, &As[cur][wm * 32 + 16][c * 16], 40);
#pragma unroll
            for (int np = 0; np < 4; ++np) {
                unsigned b[4];
                ldmB2(b, &Bs[cur][wn * 64 + np * 16][c * 16], 40);
                mmabf(acc[0][2 * np], a0, b[0], b[1]);
                mmabf(acc[0][2 * np + 1], a0, b[2], b[3]);
                mmabf(acc[1][2 * np], a1, b[0], b[1]);
                mmabf(acc[1][2 * np + 1], a1, b[2], b[3]);
            }
        }
        __syncthreads();
    }
#pragma unroll
    for (int mt = 0; mt < 2; ++mt) {
        int r0 = bm + wm * 32 + mt * 16 + (lane >> 2);
#pragma unroll
        for (int nt = 0; nt < 8; ++nt) {
            int cc = bn + wn * 64 + nt * 8 + 2 * (lane & 3);
            *(float2*)&C[(long)r0 * N + cc] = make_float2(acc[mt][nt][0], acc[mt][nt][1]);
            *(float2*)&C[(long)(r0 + 8) * N + cc] = make_float2(acc[mt][nt][2], acc[mt][nt][3]);
        }
    }
}

// ---------------- warp-per-row Mobius transform (no barriers, fp16 emit) -----
__device__ __forceinline__ float dot4(float4 a, float4 b) {
    return a.x * b.x + a.y * b.y + a.z * b.z + a.w * b.w;
}
__device__ __forceinline__ float warpSum(float v) {
#pragma unroll
    for (int o = 16; o > 0; o >>= 1) v += __shfl_xor_sync(0xffffffffu, v, o);
    return v;
}
__global__ __launch_bounds__(128) void mobius_rows(const float* __restrict__ x,
                                                   const float* __restrict__ mx, long mxs,
                                                   const float* __restrict__ bias,
                                                   float* __restrict__ out,
                                                   float* __restrict__ hn,
                                                   __half* __restrict__ ohi) {
    const int lane = threadIdx.x & 31, w = threadIdx.x >> 5;
    const long r = blockIdx.x * 4 + w;
    const float4* xp = (const float4*)(x + r * EDIM);
    const float4* mp = (const float4*)(mx + r * mxs);
    const float4* bp = (const float4*)bias;

    float4 xv[4], mv[4], bv[4];
#pragma unroll
    for (int j = 0; j < 4; ++j) {
        xv[j] = xp[lane + 32 * j];
        mv[j] = mp[lane + 32 * j];
        bv[j] = bp[lane + 32 * j];
    }
    float x2 = 0.0f, m2 = 0.0f;
#pragma unroll
    for (int j = 0; j < 4; ++j) { x2 += dot4(xv[j], xv[j]); m2 += dot4(mv[j], mv[j]); }
    x2 = warpSum(x2); m2 = warpSum(m2);

    float xn = fmaxf(sqrtf(x2), 1e-15f);
    float mn = fmaxf(sqrtf(m2), 1e-15f);
    float u = fminf(xn, 1.0f - 1e-7f);
    float at = 0.5f * (log1pf(u) - log1pf(-u));
    float tt = tanhf(mn / xn * at);
    float sc = tt / mn;
    float rn = fmaxf(tt, 1e-15f);
    float pf = (rn > MAXNORM) ? (MAXNORM / rn) : 1.0f;
    float spf = sc * pf;

    float4 res[4];
#pragma unroll
    for (int j = 0; j < 4; ++j)
        res[j] = make_float4(mv[j].x * spf, mv[j].y * spf, mv[j].z * spf, mv[j].w * spf);

    float x2r = 0.0f, y2 = 0.0f, xy = 0.0f;
#pragma unroll
    for (int j = 0; j < 4; ++j) {
        x2r += dot4(res[j], res[j]);
        y2 += dot4(bv[j], bv[j]);
        xy += dot4(res[j], bv[j]);
    }
    x2r = warpSum(x2r); y2 = warpSum(y2); xy = warpSum(xy);

    float ca = 1.0f + 2.0f * xy + y2, cb = 1.0f - x2r;
    float den = fmaxf(1.0f + 2.0f * xy + x2r * y2, 1e-15f);
    float inv = 1.0f / den;
    float4 o[4];
    float o2 = 0.0f;
#pragma unroll
    for (int j = 0; j < 4; ++j) {
        o[j] = make_float4((ca * res[j].x + cb * bv[j].x) * inv,
                           (ca * res[j].y + cb * bv[j].y) * inv,
                           (ca * res[j].z + cb * bv[j].z) * inv,
                           (ca * res[j].w + cb * bv[j].w) * inv);
        o2 += dot4(o[j], o[j]);
    }
    o2 = warpSum(o2);
    float on = fmaxf(sqrtf(o2), 1e-15f);
    float pf2 = (on > MAXNORM) ? (MAXNORM / on) : 1.0f;
#pragma unroll
    for (int j = 0; j < 4; ++j) {
        o[j].x *= pf2; o[j].y *= pf2; o[j].z *= pf2; o[j].w *= pf2;
    }

    if (out) {
        float4* op = (float4*)(out + r * EDIM);
#pragma unroll
        for (int j = 0; j < 4; ++j) op[lane + 32 * j] = o[j];
    }

    if (ohi) {
#pragma unroll
        for (int j = 0; j < 4; ++j) {
            unsigned hp0 = packh2(o[j].x, o[j].y);
            unsigned hp1 = packh2(o[j].z, o[j].w);
            *(uint2*)(ohi + r * EDIM + (lane + 32 * j) * 4) = make_uint2(hp0, hp1);
        }
    }

    if (hn) {
        int bb = (int)(r / SEQ), s = (int)(r % SEQ);
#pragma unroll
        for (int j = 0; j < 4; ++j) {
            float hs = dot4(o[j], o[j]);
#pragma unroll
            for (int off = 8; off >= 1; off >>= 1)
                hs += __shfl_xor_sync(0xffffffffu, hs, off, 16);
            if ((lane & 15) == 0) {
                int head = (lane >> 4) + 2 * j;
                hn[((long)bb * NH + head) * SEQ + s] = fminf(hs, 1.0f - 1e-5f);
            }
        }
    }
}

// ---------------- flash hyperbolic attention v6: fp16 Q/K/V/P ----------------
#define AP 72
#define KVU (64 * AP)
#define BUF2 (2 * KVU)           // K + V
#define ASMB6 ((128 * AP + 2 * BUF2) * 2 + (128 + 2 * 64) * 4)
#define SCLAMP2 (-5.702734e-4f)  // -sqrt(1e-5)/8 * log2(e)
#define SC2 (-0.1803368801f)     // -0.125 * log2(e)

__global__ void __launch_bounds__(256, 2) attn6(const __half* __restrict__ qh,
                                                const __half* __restrict__ kh,
                                                const __half* __restrict__ vh,
                                                const float* __restrict__ qn,
                                                const float* __restrict__ kn,
                                                float* __restrict__ o) {
    extern __shared__ __half hsm[];
    __half* Qs = hsm;
    __half* bufs[2] = { hsm + 128 * AP, hsm + 128 * AP + BUF2 };
    float* qns = (float*)(hsm + 128 * AP + 2 * BUF2);
    float* kns = qns + 128;

    const int tid = threadIdx.x, lane = tid & 31, w = tid >> 5;
    const int bh = blockIdx.y, b = bh >> 3, h = bh & 7;
    const int q0 = blockIdx.x * 128;
    const long qrow0 = (long)b * SEQ + q0;

#pragma unroll
    for (int it = 0; it < 4; ++it) {
        int slot = tid + it * 256;
        int r = slot >> 3, c8 = (slot & 7) * 8;
        *(uint4*)&Qs[r * AP + c8] = *(const uint4*)&qh[(qrow0 + r) * EDIM + h * DH + c8];
    }
    if (tid < 128) qns[tid] = qn[(long)bh * SEQ + q0 + tid];

    {
        const long krow0 = (long)b * SEQ;
#pragma unroll
        for (int it = 0; it < 2; ++it) {
            int slot = tid + it * 256;
            int r = slot >> 3, c8 = (slot & 7) * 8;
            long g = (krow0 + r) * EDIM + h * DH + c8;
            cpa16(&bufs[0][r * AP + c8], kh + g);
            cpa16(&bufs[0][KVU + r * AP + c8], vh + g);
        }
        if (tid < 16) cpa16(&kns[tid * 4], kn + (long)bh * SEQ + tid * 4);
        asm volatile("cp.async.commit_group;");
    }
    __syncthreads();

    const float qv0 = qns[w * 16 + (lane >> 2)];
    const float qv1 = qns[w * 16 + (lane >> 2) + 8];
    const float oq0 = 1.0f - qv0, oq1 = 1.0f - qv1;

    float O[8][4] = {};
    float ls0 = 0.0f, ls1 = 0.0f;

    for (int t = 0; t < 32; ++t) {
        const int cur = t & 1;
        if (t + 1 < 32) {
            const long krow0 = (long)b * SEQ + (t + 1) * 64;
            __half* nb = bufs[1 - cur];
#pragma unroll
            for (int it = 0; it < 2; ++it) {
                int slot = tid + it * 256;
                int r = slot >> 3, c8 = (slot & 7) * 8;
                long g = (krow0 + r) * EDIM + h * DH + c8;
                cpa16(&nb[r * AP + c8], kh + g);
                cpa16(&nb[KVU + r * AP + c8], vh + g);
            }
            if (tid < 16) cpa16(&kns[(1 - cur) * 64 + tid * 4],
                                kn + (long)bh * SEQ + (t + 1) * 64 + tid * 4);
            asm volatile("cp.async.commit_group;");
            asm volatile("cp.async.wait_group 1;");
        } else {
            asm volatile("cp.async.wait_group 0;");
        }
        __syncthreads();

        const __half* Kt = bufs[cur];
        const __half* Vt = bufs[cur] + KVU;
        const float* knt = kns + cur * 64;

        // S = Q K^T (fp16, K=64)
        float c[8][4] = {};
#pragma unroll
        for (int cs = 0; cs < 4; ++cs) {
            unsigned a[4];
            ldmA(a, Qs + (w * 16) * AP + cs * 16, AP);
#pragma unroll
            for (int np = 0; np < 4; ++np) {
                unsigned bb[4];
                ldmB2(bb, Kt + (np * 16) * AP + cs * 16, AP);
                mmaf16(c[2 * np], a, bb[0], bb[1]);
                mmaf16(c[2 * np + 1], a, bb[2], bb[3]);
            }
        }

        // hyperbolic score -> p = exp2(score*log2e) (m = 0)
#pragma unroll
        for (int nt = 0; nt < 8; ++nt) {
#pragma unroll
            for (int e = 0; e < 4; ++e) {
                int col = nt * 8 + 2 * (lane & 3) + (e & 1);
                float kv = knt[col];
                float qq = (e < 2) ? qv0 : qv1;
                float oq = (e < 2) ? oq0 : oq1;
                float t2 = 2.0f * fmaf(-qq, kv, c[nt][e]);
                float dn = fmaf(oq, 1.0f - kv, 1e-5f);
                float s = t2 * __frsqrt_rn(t2 * dn) * SC2;
                if (t2 <= 1e-5f * dn) s = SCLAMP2;
                float p = ex2f(s);
                c[nt][e] = p;
                if (e < 2) ls0 += p; else ls1 += p;
            }
        }

        // O += P V (fp16 single pass)
#pragma unroll
        for (int s = 0; s < 4; ++s) {
            unsigned AH[4];
#pragma unroll
            for (int half = 0; half < 2; ++half) {
                int t_ = 2 * s + half;
                AH[2 * half]     = packh2(c[t_][0], c[t_][1]);
                AH[2 * half + 1] = packh2(c[t_][2], c[t_][3]);
            }
#pragma unroll
            for (int np = 0; np < 4; ++np) {
                unsigned bh_[4];
                ldmBt(bh_, Vt + (s * 16) * AP + np * 16, AP);
                mmaf16(O[2 * np],     AH, bh_[0], bh_[1]);
                mmaf16(O[2 * np + 1], AH, bh_[2], bh_[3]);
            }
        }
        __syncthreads();
    }

    ls0 += __shfl_xor_sync(0xffffffffu, ls0, 1);
    ls0 += __shfl_xor_sync(0xffffffffu, ls0, 2);
    ls1 += __shfl_xor_sync(0xffffffffu, ls1, 1);
    ls1 += __shfl_xor_sync(0xffffffffu, ls1, 2);
    float il0 = 1.0f / ls0, il1 = 1.0f / ls1;

    int r0 = q0 + w * 16 + (lane >> 2);
    float* ob = o + ((long)b * SEQ + r0) * EDIM + h * DH;
#pragma unroll
    for (int nt = 0; nt < 8; ++nt) {
        int cc = nt * 8 + 2 * (lane & 3);
        *(float2*)(ob + cc) = make_float2(O[nt][0] * il0, O[nt][1] * il0);
        *(float2*)(ob + 8L * EDIM + cc) = make_float2(O[nt][2] * il1, O[nt][3] * il1);
    }
}

// ---------------- launch ----------------
extern "C" void kernel_launch(void* const* d_in, const int* in_sizes, int n_in,
                              void* d_out, int out_size) {
    const float* x  = (const float*)d_in[0];
    const float* Wq = (const float*)d_in[1];
    const float* bq = (const float*)d_in[2];
    const float* Wk = (const float*)d_in[3];
    const float* bk = (const float*)d_in[4];
    const float* Wv = (const float*)d_in[5];
    const float* bv = (const float*)d_in[6];
    const float* Wo = (const float*)d_in[7];
    const float* bo = (const float*)d_in[8];
    float* out = (float*)d_out;

    float *qkv, *st, *ao, *qn, *kn;
    __nv_bfloat16 *xcat, *wcat;
    __half *qhb, *khb, *vhb;
    cudaGetSymbolAddress((void**)&qkv, g_qkv);
    cudaGetSymbolAddress((void**)&st, g_st);
    cudaGetSymbolAddress((void**)&ao, g_ao);
    cudaGetSymbolAddress((void**)&qn, g_qn);
    cudaGetSymbolAddress((void**)&kn, g_kn);
    cudaGetSymbolAddress((void**)&xcat, g_xcat);
    cudaGetSymbolAddress((void**)&wcat, g_wcat);
    cudaGetSymbolAddress((void**)&qhb, g_qh);
    cudaGetSymbolAddress((void**)&khb, g_kh);
    cudaGetSymbolAddress((void**)&vhb, g_vh);

    cudaFuncSetAttribute(attn6, cudaFuncAttributeMaxDynamicSharedMemorySize, ASMB6);

    const long n2w = (long)EDIM * EDIM / 2;
    const long n2x = (long)ROWS * EDIM / 2;
    const long WSTR = (long)EDIM * KCAT;

    dim3 gw((unsigned)((n2w + 255) / 256), 4);
    split_cat_w<<<gw, 256>>>(Wq, Wk, Wv, Wo, wcat, n2w);
    split_cat<<<(unsigned)((n2x + 255) / 256), 256>>>(x, xcat, n2x, 0);

    dim3 gq(3 * EDIM / 128, ROWS / 128);   // (12, 64)
    gemm_bf16<<<gq, 256>>>(xcat, wcat, qkv, ROWS, 3 * EDIM, KCAT);

    mobius_rows<<<ROWS / 4, 128>>>(x, qkv + 0 * EDIM, 3 * EDIM, bq, nullptr, qn, qhb);
    mobius_rows<<<ROWS / 4, 128>>>(x, qkv + 1 * EDIM, 3 * EDIM, bk, nullptr, kn, khb);
    mobius_rows<<<ROWS / 4, 128>>>(x, qkv + 2 * EDIM, 3 * EDIM, bv, nullptr, nullptr, vhb);

    dim3 ag(SEQ / 128, BH);                // (16, 32)
    attn6<<<ag, 256, ASMB6>>>(qhb, khb, vhb, qn, kn, ao);

    split_cat<<<(unsigned)((n2x + 255) / 256), 256>>>(ao, xcat, n2x, 0);
    dim3 go(EDIM / 128, ROWS / 128);       // (4, 64)
    gemm_bf16<<<go, 256>>>(xcat, wcat + 3 * WSTR, st, ROWS, EDIM, KCAT);
    mobius_rows<<<ROWS / 4, 128>>>(ao, st, EDIM, bo, out, nullptr, nullptr);
}

// round 15
// speedup vs baseline: 1.7549x; 1.1642x over previous
#include <cuda_runtime.h>
#include <cuda_fp16.h>
#include <math.h>

#define EDIM 512
#define BDIM 4
#define SEQ  2048
#define NH   8
#define DH   64
#define ROWS (BDIM*SEQ)
#define BH   (BDIM*NH)
#define KC2  1024                 // fp16 2-term split-K
#define MAXNORM (1.0f - 4e-3f)

// ---------------- scratch ----------------
__device__ float g_qkv[(long)ROWS*3*EDIM];
__device__ float g_st[ROWS*EDIM];
__device__ float g_ao[ROWS*EDIM];
__device__ __half g_xcat[(long)ROWS*KC2];
__device__ __half g_wcat[4L*EDIM*KC2];
__device__ __half g_qh[ROWS*EDIM];
__device__ __half g_kh[ROWS*EDIM];
__device__ __half g_vh[ROWS*EDIM];
__device__ float g_qn[BH*SEQ];
__device__ float g_kn[BH*SEQ];

// ---------------- mma helpers ----------------
__device__ __forceinline__ void ldmA(unsigned r[4], const void* p0v, int pitch) {
    const __half* p0 = (const __half*)p0v;
    int l = threadIdx.x & 31;
    unsigned a = (unsigned)__cvta_generic_to_shared(p0 + (l & 15) * pitch + ((l >> 4) << 3));
    asm volatile("ldmatrix.sync.aligned.m8n8.x4.shared.b16 {%0,%1,%2,%3}, [%4];"
                 : "=r"(r[0]), "=r"(r[1]), "=r"(r[2]), "=r"(r[3]) : "r"(a));
}
__device__ __forceinline__ void ldmB2(unsigned r[4], const void* p0v, int pitch) {
    const __half* p0 = (const __half*)p0v;
    int l = threadIdx.x & 31;
    unsigned a = (unsigned)__cvta_generic_to_shared(p0 + ((l & 7) + ((l >> 4) << 3)) * pitch + (l & 8));
    asm volatile("ldmatrix.sync.aligned.m8n8.x4.shared.b16 {%0,%1,%2,%3}, [%4];"
                 : "=r"(r[0]), "=r"(r[1]), "=r"(r[2]), "=r"(r[3]) : "r"(a));
}
__device__ __forceinline__ void ldmBt(unsigned r[4], const void* p0v, int pitch) {
    const __half* p0 = (const __half*)p0v;
    int l = threadIdx.x & 31;
    unsigned a = (unsigned)__cvta_generic_to_shared(
        p0 + ((l & 7) + ((l >> 3) & 1) * 8) * pitch + ((l >> 4) << 3));
    asm volatile("ldmatrix.sync.aligned.m8n8.x4.trans.shared.b16 {%0,%1,%2,%3}, [%4];"
                 : "=r"(r[0]), "=r"(r[1]), "=r"(r[2]), "=r"(r[3]) : "r"(a));
}
__device__ __forceinline__ void mmaf16(float c[4], const unsigned a[4], unsigned b0, unsigned b1) {
    asm volatile("mma.sync.aligned.m16n8k16.row.col.f32.f16.f16.f32 "
                 "{%0,%1,%2,%3},{%4,%5,%6,%7},{%8,%9},{%0,%1,%2,%3};"
                 : "+f"(c[0]), "+f"(c[1]), "+f"(c[2]), "+f"(c[3])
                 : "r"(a[0]), "r"(a[1]), "r"(a[2]), "r"(a[3]), "r"(b0), "r"(b1));
}
__device__ __forceinline__ unsigned packh2(float lo, float hi) {
    __half2 h = __floats2half2_rn(lo, hi);
    return *(unsigned*)&h;
}
__device__ __forceinline__ void cpa16(void* s, const void* g) {
    unsigned a = (unsigned)__cvta_generic_to_shared(s);
    asm volatile("cp.async.cg.shared.global [%0], [%1], 16;" :: "r"(a), "l"(g));
}
__device__ __forceinline__ float ex2f(float x) {
    float r;
    asm("ex2.approx.f32 %0, %1;" : "=f"(r) : "f"(x));
    return r;
}

// ---------------- fp16 splits: x -> [hi|lo], W -> [hi|hi] ----------------
__device__ __forceinline__ void split_f16(const float* __restrict__ src,
                                          __half* __restrict__ dst, long i, int dup) {
    long e = i * 2;
    long r = e >> 9; int c = (int)(e & 511);
    float v0 = src[e], v1 = src[e + 1];
    __half h0 = __float2half_rn(v0), h1 = __float2half_rn(v1);
    __half* p = dst + r * KC2 + c;
    p[0] = h0; p[1] = h1;
    if (dup) { p[512] = h0; p[513] = h1; }
    else {
        p[512] = __float2half_rn(v0 - __half2float(h0));
        p[513] = __float2half_rn(v1 - __half2float(h1));
    }
}
__global__ __launch_bounds__(256) void split_x(const float* __restrict__ src,
                                               __half* __restrict__ dst, long n2) {
    long i = (long)blockIdx.x * blockDim.x + threadIdx.x;
    if (i >= n2) return;
    split_f16(src, dst, i, 0);
}
__global__ __launch_bounds__(256) void split_w(const float* __restrict__ w0,
                                               const float* __restrict__ w1,
                                               const float* __restrict__ w2,
                                               const float* __restrict__ w3,
                                               __half* __restrict__ dst, long n2) {
    long i = (long)blockIdx.x * blockDim.x + threadIdx.x;
    if (i >= n2) return;
    const float* srcs[4] = {w0, w1, w2, w3};
    split_f16(srcs[blockIdx.y], dst + (long)blockIdx.y * EDIM * KC2, i, 1);
}

// ---------------- fp16 NT GEMM, cp.async 2-stage: C fp32 = A[M,K] @ B[N,K]^T ----
__global__ __launch_bounds__(256) void gemm_f16(const __half* __restrict__ A,
                                                const __half* __restrict__ B,
                                                float* __restrict__ C,
                                                int M, int N, int K) {
    __shared__ __align__(16) __half As[2][128][40];
    __shared__ __align__(16) __half Bs[2][128][40];
    const int tid = threadIdx.x, lane = tid & 31, wid = tid >> 5;
    const int wm = wid & 3, wn = wid >> 2;
    const int bm = blockIdx.y * 128, bn = blockIdx.x * 128;

#pragma unroll
    for (int i = 0; i < 2; ++i) {
        int slot = tid + i * 256;
        int row = slot >> 2, ch = (slot & 3) * 8;
        cpa16(&As[0][row][ch], &A[(long)(bm + row) * K + ch]);
        cpa16(&Bs[0][row][ch], &B[(long)(bn + row) * K + ch]);
    }
    asm volatile("cp.async.commit_group;");

    const int T = K / 32;
    float acc[2][8][4] = {};
    for (int t = 0; t < T; ++t) {
        const int cur = t & 1;
        if (t + 1 < T) {
            const int kt = (t + 1) * 32;
#pragma unroll
            for (int i = 0; i < 2; ++i) {
                int slot = tid + i * 256;
                int row = slot >> 2, ch = (slot & 3) * 8;
                cpa16(&As[1 - cur][row][ch], &A[(long)(bm + row) * K + kt + ch]);
                cpa16(&Bs[1 - cur][row][ch], &B[(long)(bn + row) * K + kt + ch]);
            }
            asm volatile("cp.async.commit_group;");
            asm volatile("cp.async.wait_group 1;");
        } else {
            asm volatile("cp.async.wait_group 0;");
        }
        __syncthreads();
#pragma unroll
        for (int c = 0; c < 2; ++c) {
            unsigned a0[4], a1[4];
            ldmA(a0, &As[cur][wm * 32][c * 16], 40);
            ldmA(a1, &As[cur][wm * 32 + 16][c * 16], 40);
#pragma unroll
            for (int np = 0; np < 4; ++np) {
                unsigned b[4];
                ldmB2(b, &Bs[cur][wn * 64 + np * 16][c * 16], 40);
                mmaf16(acc[0][2 * np], a0, b[0], b[1]);
                mmaf16(acc[0][2 * np + 1], a0, b[2], b[3]);
                mmaf16(acc[1][2 * np], a1, b[0], b[1]);
                mmaf16(acc[1][2 * np + 1], a1, b[2], b[3]);
            }
        }
        __syncthreads();
    }
#pragma unroll
    for (int mt = 0; mt < 2; ++mt) {
        int r0 = bm + wm * 32 + mt * 16 + (lane >> 2);
#pragma unroll
        for (int nt = 0; nt < 8; ++nt) {
            int cc = bn + wn * 64 + nt * 8 + 2 * (lane & 3);
            *(float2*)&C[(long)r0 * N + cc] = make_float2(acc[mt][nt][0], acc[mt][nt][1]);
            *(float2*)&C[(long)(r0 + 8) * N + cc] = make_float2(acc[mt][nt][2], acc[mt][nt][3]);
        }
    }
}

// ---------------- warp-per-row Mobius transform core ----------------
__device__ __forceinline__ float dot4(float4 a, float4 b) {
    return a.x * b.x + a.y * b.y + a.z * b.z + a.w * b.w;
}
__device__ __forceinline__ float warpSum(float v) {
#pragma unroll
    for (int o = 16; o > 0; o >>= 1) v += __shfl_xor_sync(0xffffffffu, v, o);
    return v;
}
__device__ void mobius_core(const float* __restrict__ x,
                            const float* __restrict__ mx, long mxs,
                            const float* __restrict__ bias,
                            float* __restrict__ out,
                            float* __restrict__ hn,
                            __half* __restrict__ ohi) {
    const int lane = threadIdx.x & 31, w = threadIdx.x >> 5;
    const long r = blockIdx.x * 4 + w;
    const float4* xp = (const float4*)(x + r * EDIM);
    const float4* mp = (const float4*)(mx + r * mxs);
    const float4* bp = (const float4*)bias;

    float4 xv[4], mv[4], bv[4];
#pragma unroll
    for (int j = 0; j < 4; ++j) {
        xv[j] = xp[lane + 32 * j];
        mv[j] = mp[lane + 32 * j];
        bv[j] = bp[lane + 32 * j];
    }
    float x2 = 0.0f, m2 = 0.0f;
#pragma unroll
    for (int j = 0; j < 4; ++j) { x2 += dot4(xv[j], xv[j]); m2 += dot4(mv[j], mv[j]); }
    x2 = warpSum(x2); m2 = warpSum(m2);

    float xn = fmaxf(sqrtf(x2), 1e-15f);
    float mn = fmaxf(sqrtf(m2), 1e-15f);
    float u = fminf(xn, 1.0f - 1e-7f);
    float at = 0.5f * (log1pf(u) - log1pf(-u));
    float tt = tanhf(mn / xn * at);
    float sc = tt / mn;
    float rn = fmaxf(tt, 1e-15f);
    float pf = (rn > MAXNORM) ? (MAXNORM / rn) : 1.0f;
    float spf = sc * pf;

    float4 res[4];
#pragma unroll
    for (int j = 0; j < 4; ++j)
        res[j] = make_float4(mv[j].x * spf, mv[j].y * spf, mv[j].z * spf, mv[j].w * spf);

    float x2r = 0.0f, y2 = 0.0f, xy = 0.0f;
#pragma unroll
    for (int j = 0; j < 4; ++j) {
        x2r += dot4(res[j], res[j]);
        y2 += dot4(bv[j], bv[j]);
        xy += dot4(res[j], bv[j]);
    }
    x2r = warpSum(x2r); y2 = warpSum(y2); xy = warpSum(xy);

    float ca = 1.0f + 2.0f * xy + y2, cb = 1.0f - x2r;
    float den = fmaxf(1.0f + 2.0f * xy + x2r * y2, 1e-15f);
    float inv = 1.0f / den;
    float4 o[4];
    float o2 = 0.0f;
#pragma unroll
    for (int j = 0; j < 4; ++j) {
        o[j] = make_float4((ca * res[j].x + cb * bv[j].x) * inv,
                           (ca * res[j].y + cb * bv[j].y) * inv,
                           (ca * res[j].z + cb * bv[j].z) * inv,
                           (ca * res[j].w + cb * bv[j].w) * inv);
        o2 += dot4(o[j], o[j]);
    }
    o2 = warpSum(o2);
    float on = fmaxf(sqrtf(o2), 1e-15f);
    float pf2 = (on > MAXNORM) ? (MAXNORM / on) : 1.0f;
#pragma unroll
    for (int j = 0; j < 4; ++j) {
        o[j].x *= pf2; o[j].y *= pf2; o[j].z *= pf2; o[j].w *= pf2;
    }

    if (out) {
        float4* op = (float4*)(out + r * EDIM);
#pragma unroll
        for (int j = 0; j < 4; ++j) op[lane + 32 * j] = o[j];
    }
    if (ohi) {
#pragma unroll
        for (int j = 0; j < 4; ++j) {
            unsigned hp0 = packh2(o[j].x, o[j].y);
            unsigned hp1 = packh2(o[j].z, o[j].w);
            *(uint2*)(ohi + r * EDIM + (lane + 32 * j) * 4) = make_uint2(hp0, hp1);
        }
    }
    if (hn) {
        int bb = (int)(r / SEQ), s = (int)(r % SEQ);
#pragma unroll
        for (int j = 0; j < 4; ++j) {
            float hs = dot4(o[j], o[j]);
#pragma unroll
            for (int off = 8; off >= 1; off >>= 1)
                hs += __shfl_xor_sync(0xffffffffu, hs, off, 16);
            if ((lane & 15) == 0) {
                int head = (lane >> 4) + 2 * j;
                hn[((long)bb * NH + head) * SEQ + s] = fminf(hs, 1.0f - 1e-5f);
            }
        }
    }
}
// q and k fused (blockIdx.y selects)
__global__ __launch_bounds__(128) void mobius_qk(const float* __restrict__ x,
                                                 const float* __restrict__ qkv,
                                                 const float* __restrict__ bq,
                                                 const float* __restrict__ bk,
                                                 float* __restrict__ qn,
                                                 float* __restrict__ kn,
                                                 __half* __restrict__ qhb,
                                                 __half* __restrict__ khb) {
    int sel = blockIdx.y;
    mobius_core(x, qkv + sel * EDIM, 3 * EDIM, sel ? bk : bq,
                nullptr, sel ? kn : qn, sel ? khb : qhb);
}
__global__ __launch_bounds__(128) void mobius_one(const float* __restrict__ x,
                                                  const float* __restrict__ mx, long mxs,
                                                  const float* __restrict__ bias,
                                                  float* __restrict__ out,
                                                  __half* __restrict__ ohi) {
    mobius_core(x, mx, mxs, bias, out, nullptr, ohi);
}

// ---------------- flash hyperbolic attention v6 (fp16, streamlined scores) ----
#define AP 72
#define KVU (64 * AP)
#define BUF2 (2 * KVU)
#define ASMB6 ((128 * AP + 2 * BUF2) * 2 + (128 + 2 * 64) * 4)
#define SCLAMP2 (-5.702734e-4f)   // -sqrt(1e-5)/8 * log2(e)
#define SC3 (-0.25503343f)        // -0.125 * log2(e) * sqrt(2)

__global__ void __launch_bounds__(256, 2) attn6(const __half* __restrict__ qh,
                                                const __half* __restrict__ kh,
                                                const __half* __restrict__ vh,
                                                const float* __restrict__ qn,
                                                const float* __restrict__ kn,
                                                float* __restrict__ o) {
    extern __shared__ __half hsm[];
    __half* Qs = hsm;
    __half* bufs[2] = { hsm + 128 * AP, hsm + 128 * AP + BUF2 };
    float* qns = (float*)(hsm + 128 * AP + 2 * BUF2);
    float* kns = qns + 128;

    const int tid = threadIdx.x, lane = tid & 31, w = tid >> 5;
    const int bh = blockIdx.y, b = bh >> 3, h = bh & 7;
    const int q0 = blockIdx.x * 128;
    const long qrow0 = (long)b * SEQ + q0;

#pragma unroll
    for (int it = 0; it < 4; ++it) {
        int slot = tid + it * 256;
        int r = slot >> 3, c8 = (slot & 7) * 8;
        *(uint4*)&Qs[r * AP + c8] = *(const uint4*)&qh[(qrow0 + r) * EDIM + h * DH + c8];
    }
    if (tid < 128) qns[tid] = qn[(long)bh * SEQ + q0 + tid];

    {
        const long krow0 = (long)b * SEQ;
#pragma unroll
        for (int it = 0; it < 2; ++it) {
            int slot = tid + it * 256;
            int r = slot >> 3, c8 = (slot & 7) * 8;
            long g = (krow0 + r) * EDIM + h * DH + c8;
            cpa16(&bufs[0][r * AP + c8], kh + g);
            cpa16(&bufs[0][KVU + r * AP + c8], vh + g);
        }
        if (tid < 16) cpa16(&kns[tid * 4], kn + (long)bh * SEQ + tid * 4);
        asm volatile("cp.async.commit_group;");
    }
    __syncthreads();

    const float qv0 = qns[w * 16 + (lane >> 2)];
    const float qv1 = qns[w * 16 + (lane >> 2) + 8];
    const float oq0 = 1.0f - qv0, oq1 = 1.0f - qv1;
    const float oq0p = oq0 + 1e-5f, oq1p = oq1 + 1e-5f;

    float O[8][4] = {};
    float ls0 = 0.0f, ls1 = 0.0f;

    for (int t = 0; t < 32; ++t) {
        const int cur = t & 1;
        if (t + 1 < 32) {
            const long krow0 = (long)b * SEQ + (t + 1) * 64;
            __half* nb = bufs[1 - cur];
#pragma unroll
            for (int it = 0; it < 2; ++it) {
                int slot = tid + it * 256;
                int r = slot >> 3, c8 = (slot & 7) * 8;
                long g = (krow0 + r) * EDIM + h * DH + c8;
                cpa16(&nb[r * AP + c8], kh + g);
                cpa16(&nb[KVU + r * AP + c8], vh + g);
            }
            if (tid < 16) cpa16(&kns[(1 - cur) * 64 + tid * 4],
                                kn + (long)bh * SEQ + (t + 1) * 64 + tid * 4);
            asm volatile("cp.async.commit_group;");
            asm volatile("cp.async.wait_group 1;");
        } else {
            asm volatile("cp.async.wait_group 0;");
        }
        __syncthreads();

        const __half* Kt = bufs[cur];
        const __half* Vt = bufs[cur] + KVU;
        const float* knt = kns + cur * 64;

        // S = Q K^T (fp16, K=64)
        float c[8][4] = {};
#pragma unroll
        for (int cs = 0; cs < 4; ++cs) {
            unsigned a[4];
            ldmA(a, Qs + (w * 16) * AP + cs * 16, AP);
#pragma unroll
            for (int np = 0; np < 4; ++np) {
                unsigned bb[4];
                ldmB2(bb, Kt + (np * 16) * AP + cs * 16, AP);
                mmaf16(c[2 * np], a, bb[0], bb[1]);
                mmaf16(c[2 * np + 1], a, bb[2], bb[3]);
            }
        }

        // score: s = -sqrt(2u/dn)/8, u = qk - qn*kn, dn = oq*(1-kv)+1e-5
        //   = u*rsqrt(u*dn)*(-0.125*sqrt2)  (log2e folded for ex2)
#pragma unroll
        for (int nt = 0; nt < 8; ++nt) {
#pragma unroll
            for (int e = 0; e < 4; ++e) {
                int col = nt * 8 + 2 * (lane & 3) + (e & 1);
                float kv = knt[col];
                float qq = (e < 2) ? qv0 : qv1;
                float oqp = (e < 2) ? oq0p : oq1p;
                float oq = (e < 2) ? oq0 : oq1;
                float uu = fmaf(-qq, kv, c[nt][e]);
                float dn = fmaf(-oq, kv, oqp);
                float s = uu * __frsqrt_rn(uu * dn) * SC3;
                if (uu <= 5e-6f * dn) s = SCLAMP2;
                float p = ex2f(s);
                c[nt][e] = p;
                if (e < 2) ls0 += p; else ls1 += p;
            }
        }

        // O += P V (fp16 single pass)
#pragma unroll
        for (int s = 0; s < 4; ++s) {
            unsigned AH[4];
#pragma unroll
            for (int half = 0; half < 2; ++half) {
                int t_ = 2 * s + half;
                AH[2 * half]     = packh2(c[t_][0], c[t_][1]);
                AH[2 * half + 1] = packh2(c[t_][2], c[t_][3]);
            }
#pragma unroll
            for (int np = 0; np < 4; ++np) {
                unsigned bh_[4];
                ldmBt(bh_, Vt + (s * 16) * AP + np * 16, AP);
                mmaf16(O[2 * np],     AH, bh_[0], bh_[1]);
                mmaf16(O[2 * np + 1], AH, bh_[2], bh_[3]);
            }
        }
        __syncthreads();
    }

    ls0 += __shfl_xor_sync(0xffffffffu, ls0, 1);
    ls0 += __shfl_xor_sync(0xffffffffu, ls0, 2);
    ls1 += __shfl_xor_sync(0xffffffffu, ls1, 1);
    ls1 += __shfl_xor_sync(0xffffffffu, ls1, 2);
    float il0 = 1.0f / ls0, il1 = 1.0f / ls1;

    int r0 = q0 + w * 16 + (lane >> 2);
    float* ob = o + ((long)b * SEQ + r0) * EDIM + h * DH;
#pragma unroll
    for (int nt = 0; nt < 8; ++nt) {
        int cc = nt * 8 + 2 * (lane & 3);
        *(float2*)(ob + cc) = make_float2(O[nt][0] * il0, O[nt][1] * il0);
        *(float2*)(ob + 8L * EDIM + cc) = make_float2(O[nt][2] * il1, O[nt][3] * il1);
    }
}

// ---------------- launch ----------------
extern "C" void kernel_launch(void* const* d_in, const int* in_sizes, int n_in,
                              void* d_out, int out_size) {
    const float* x  = (const float*)d_in[0];
    const float* Wq = (const float*)d_in[1];
    const float* bq = (const float*)d_in[2];
    const float* Wk = (const float*)d_in[3];
    const float* bk = (const float*)d_in[4];
    const float* Wv = (const float*)d_in[5];
    const float* bv = (const float*)d_in[6];
    const float* Wo = (const float*)d_in[7];
    const float* bo = (const float*)d_in[8];
    float* out = (float*)d_out;

    float *qkv, *st, *ao, *qn, *kn;
    __half *xcat, *wcat, *qhb, *khb, *vhb;
    cudaGetSymbolAddress((void**)&qkv, g_qkv);
    cudaGetSymbolAddress((void**)&st, g_st);
    cudaGetSymbolAddress((void**)&ao, g_ao);
    cudaGetSymbolAddress((void**)&qn, g_qn);
    cudaGetSymbolAddress((void**)&kn, g_kn);
    cudaGetSymbolAddress((void**)&xcat, g_xcat);
    cudaGetSymbolAddress((void**)&wcat, g_wcat);
    cudaGetSymbolAddress((void**)&qhb, g_qh);
    cudaGetSymbolAddress((void**)&khb, g_kh);
    cudaGetSymbolAddress((void**)&vhb, g_vh);

    cudaFuncSetAttribute(attn6, cudaFuncAttributeMaxDynamicSharedMemorySize, ASMB6);

    const long n2w = (long)EDIM * EDIM / 2;
    const long n2x = (long)ROWS * EDIM / 2;
    const long WSTR = (long)EDIM * KC2;

    dim3 gw((unsigned)((n2w + 255) / 256), 4);
    split_w<<<gw, 256>>>(Wq, Wk, Wv, Wo, wcat, n2w);                 // launch 0
    split_x<<<(unsigned)((n2x + 255) / 256), 256>>>(x, xcat, n2x);   // launch 1

    dim3 gq(3 * EDIM / 128, ROWS / 128);   // (12, 64)
    gemm_f16<<<gq, 256>>>(xcat, wcat, qkv, ROWS, 3 * EDIM, KC2);     // launch 2

    dim3 gm(ROWS / 4, 2);
    mobius_qk<<<gm, 128>>>(x, qkv, bq, bk, qn, kn, qhb, khb);        // launch 3
    mobius_one<<<ROWS / 4, 128>>>(x, qkv + 2 * EDIM, 3 * EDIM, bv, nullptr, vhb); // launch 4

    dim3 ag(SEQ / 128, BH);                // (16, 32)
    attn6<<<ag, 256, ASMB6>>>(qhb, khb, vhb, qn, kn, ao);            // launch 5 (ncu target)

    split_x<<<(unsigned)((n2x + 255) / 256), 256>>>(ao, xcat, n2x);  // launch 6
    dim3 go(EDIM / 128, ROWS / 128);       // (4, 64)
    gemm_f16<<<go, 256>>>(xcat, wcat + 3 * WSTR, st, ROWS, EDIM, KC2); // launch 7
    mobius_one<<<ROWS / 4, 128>>>(ao, st, EDIM, bo, out, nullptr);   // launch 8
}

// round 16
// speedup vs baseline: 1.8173x; 1.0356x over previous
#include <cuda_runtime.h>
#include <cuda_fp16.h>
#include <math.h>

#define EDIM 512
#define BDIM 4
#define SEQ  2048
#define NH   8
#define DH   64
#define ROWS (BDIM*SEQ)
#define BH   (BDIM*NH)
#define KC2  1024                 // fp16 2-term split-K
#define MAXNORM (1.0f - 4e-3f)

// ---------------- scratch ----------------
__device__ float g_qkv[(long)ROWS*3*EDIM];
__device__ float g_st[ROWS*EDIM];
__device__ float g_ao[ROWS*EDIM];
__device__ __half g_xcat[(long)ROWS*KC2];
__device__ __half g_wcat[4L*EDIM*KC2];
__device__ __half g_qh[ROWS*EDIM];
__device__ __half g_kh[ROWS*EDIM];
__device__ __half g_vh[ROWS*EDIM];
__device__ float g_qn[BH*SEQ];
__device__ float g_kn[BH*SEQ];

// ---------------- mma helpers ----------------
__device__ __forceinline__ void ldmA(unsigned r[4], const void* p0v, int pitch) {
    const __half* p0 = (const __half*)p0v;
    int l = threadIdx.x & 31;
    unsigned a = (unsigned)__cvta_generic_to_shared(p0 + (l & 15) * pitch + ((l >> 4) << 3));
    asm volatile("ldmatrix.sync.aligned.m8n8.x4.shared.b16 {%0,%1,%2,%3}, [%4];"
                 : "=r"(r[0]), "=r"(r[1]), "=r"(r[2]), "=r"(r[3]) : "r"(a));
}
__device__ __forceinline__ void ldmB2(unsigned r[4], const void* p0v, int pitch) {
    const __half* p0 = (const __half*)p0v;
    int l = threadIdx.x & 31;
    unsigned a = (unsigned)__cvta_generic_to_shared(p0 + ((l & 7) + ((l >> 4) << 3)) * pitch + (l & 8));
    asm volatile("ldmatrix.sync.aligned.m8n8.x4.shared.b16 {%0,%1,%2,%3}, [%4];"
                 : "=r"(r[0]), "=r"(r[1]), "=r"(r[2]), "=r"(r[3]) : "r"(a));
}
__device__ __forceinline__ void ldmBt(unsigned r[4], const void* p0v, int pitch) {
    const __half* p0 = (const __half*)p0v;
    int l = threadIdx.x & 31;
    unsigned a = (unsigned)__cvta_generic_to_shared(
        p0 + ((l & 7) + ((l >> 3) & 1) * 8) * pitch + ((l >> 4) << 3));
    asm volatile("ldmatrix.sync.aligned.m8n8.x4.trans.shared.b16 {%0,%1,%2,%3}, [%4];"
                 : "=r"(r[0]), "=r"(r[1]), "=r"(r[2]), "=r"(r[3]) : "r"(a));
}
__device__ __forceinline__ void mmaf16(float c[4], const unsigned a[4], unsigned b0, unsigned b1) {
    asm volatile("mma.sync.aligned.m16n8k16.row.col.f32.f16.f16.f32 "
                 "{%0,%1,%2,%3},{%4,%5,%6,%7},{%8,%9},{%0,%1,%2,%3};"
                 : "+f"(c[0]), "+f"(c[1]), "+f"(c[2]), "+f"(c[3])
                 : "r"(a[0]), "r"(a[1]), "r"(a[2]), "r"(a[3]), "r"(b0), "r"(b1));
}
__device__ __forceinline__ unsigned packh2(float lo, float hi) {
    __half2 h = __floats2half2_rn(lo, hi);
    return *(unsigned*)&h;
}
__device__ __forceinline__ void cpa16(void* s, const void* g) {
    unsigned a = (unsigned)__cvta_generic_to_shared(s);
    asm volatile("cp.async.cg.shared.global [%0], [%1], 16;" :: "r"(a), "l"(g));
}
__device__ __forceinline__ float ex2f(float x) {
    float r;
    asm("ex2.approx.f32 %0, %1;" : "=f"(r) : "f"(x));
    return r;
}

// ---------------- fp16 splits: x -> [hi|lo], W -> [hi|hi] ----------------
__device__ __forceinline__ void split_f16(const float* __restrict__ src,
                                          __half* __restrict__ dst, long i, int dup) {
    long e = i * 2;
    long r = e >> 9; int c = (int)(e & 511);
    float v0 = src[e], v1 = src[e + 1];
    __half h0 = __float2half_rn(v0), h1 = __float2half_rn(v1);
    __half* p = dst + r * KC2 + c;
    p[0] = h0; p[1] = h1;
    if (dup) { p[512] = h0; p[513] = h1; }
    else {
        p[512] = __float2half_rn(v0 - __half2float(h0));
        p[513] = __float2half_rn(v1 - __half2float(h1));
    }
}
__global__ __launch_bounds__(256) void split_x(const float* __restrict__ src,
                                               __half* __restrict__ dst, long n2) {
    long i = (long)blockIdx.x * blockDim.x + threadIdx.x;
    if (i >= n2) return;
    split_f16(src, dst, i, 0);
}
__global__ __launch_bounds__(256) void split_w(const float* __restrict__ w0,
                                               const float* __restrict__ w1,
                                               const float* __restrict__ w2,
                                               const float* __restrict__ w3,
                                               __half* __restrict__ dst, long n2) {
    long i = (long)blockIdx.x * blockDim.x + threadIdx.x;
    if (i >= n2) return;
    const float* srcs[4] = {w0, w1, w2, w3};
    split_f16(srcs[blockIdx.y], dst + (long)blockIdx.y * EDIM * KC2, i, 1);
}

// ---------------- fp16 NT GEMM, cp.async 2-stage: C fp32 = A[M,K] @ B[N,K]^T ----
__global__ __launch_bounds__(256) void gemm_f16(const __half* __restrict__ A,
                                                const __half* __restrict__ B,
                                                float* __restrict__ C,
                                                int M, int N, int K) {
    __shared__ __align__(16) __half As[2][128][40];
    __shared__ __align__(16) __half Bs[2][128][40];
    const int tid = threadIdx.x, lane = tid & 31, wid = tid >> 5;
    const int wm = wid & 3, wn = wid >> 2;
    const int bm = blockIdx.y * 128, bn = blockIdx.x * 128;

#pragma unroll
    for (int i = 0; i < 2; ++i) {
        int slot = tid + i * 256;
        int row = slot >> 2, ch = (slot & 3) * 8;
        cpa16(&As[0][row][ch], &A[(long)(bm + row) * K + ch]);
        cpa16(&Bs[0][row][ch], &B[(long)(bn + row) * K + ch]);
    }
    asm volatile("cp.async.commit_group;");

    const int T = K / 32;
    float acc[2][8][4] = {};
    for (int t = 0; t < T; ++t) {
        const int cur = t & 1;
        if (t + 1 < T) {
            const int kt = (t + 1) * 32;
#pragma unroll
            for (int i = 0; i < 2; ++i) {
                int slot = tid + i * 256;
                int row = slot >> 2, ch = (slot & 3) * 8;
                cpa16(&As[1 - cur][row][ch], &A[(long)(bm + row) * K + kt + ch]);
                cpa16(&Bs[1 - cur][row][ch], &B[(long)(bn + row) * K + kt + ch]);
            }
            asm volatile("cp.async.commit_group;");
            asm volatile("cp.async.wait_group 1;");
        } else {
            asm volatile("cp.async.wait_group 0;");
        }
        __syncthreads();
#pragma unroll
        for (int c = 0; c < 2; ++c) {
            unsigned a0[4], a1[4];
            ldmA(a0, &As[cur][wm * 32][c * 16], 40);
            ldmA(a1, &As[cur][wm * 32 + 16][c * 16], 40);
#pragma unroll
            for (int np = 0; np < 4; ++np) {
                unsigned b[4];
                ldmB2(b, &Bs[cur][wn * 64 + np * 16][c * 16], 40);
                mmaf16(acc[0][2 * np], a0, b[0], b[1]);
                mmaf16(acc[0][2 * np + 1], a0, b[2], b[3]);
                mmaf16(acc[1][2 * np], a1, b[0], b[1]);
                mmaf16(acc[1][2 * np + 1], a1, b[2], b[3]);
            }
        }
        __syncthreads();
    }
#pragma unroll
    for (int mt = 0; mt < 2; ++mt) {
        int r0 = bm + wm * 32 + mt * 16 + (lane >> 2);
#pragma unroll
        for (int nt = 0; nt < 8; ++nt) {
            int cc = bn + wn * 64 + nt * 8 + 2 * (lane & 3);
            *(float2*)&C[(long)r0 * N + cc] = make_float2(acc[mt][nt][0], acc[mt][nt][1]);
            *(float2*)&C[(long)(r0 + 8) * N + cc] = make_float2(acc[mt][nt][2], acc[mt][nt][3]);
        }
    }
}

// ---------------- warp-per-row Mobius transform core ----------------
__device__ __forceinline__ float dot4(float4 a, float4 b) {
    return a.x * b.x + a.y * b.y + a.z * b.z + a.w * b.w;
}
__device__ __forceinline__ float warpSum(float v) {
#pragma unroll
    for (int o = 16; o > 0; o >>= 1) v += __shfl_xor_sync(0xffffffffu, v, o);
    return v;
}
__device__ void mobius_core(const float* __restrict__ x,
                            const float* __restrict__ mx, long mxs,
                            const float* __restrict__ bias,
                            float* __restrict__ out,
                            float* __restrict__ hn,
                            __half* __restrict__ ohi) {
    const int lane = threadIdx.x & 31, w = threadIdx.x >> 5;
    const long r = blockIdx.x * 4 + w;
    const float4* xp = (const float4*)(x + r * EDIM);
    const float4* mp = (const float4*)(mx + r * mxs);
    const float4* bp = (const float4*)bias;

    float4 xv[4], mv[4], bv[4];
#pragma unroll
    for (int j = 0; j < 4; ++j) {
        xv[j] = xp[lane + 32 * j];
        mv[j] = mp[lane + 32 * j];
        bv[j] = bp[lane + 32 * j];
    }
    float x2 = 0.0f, m2 = 0.0f;
#pragma unroll
    for (int j = 0; j < 4; ++j) { x2 += dot4(xv[j], xv[j]); m2 += dot4(mv[j], mv[j]); }
    x2 = warpSum(x2); m2 = warpSum(m2);

    float xn = fmaxf(sqrtf(x2), 1e-15f);
    float mn = fmaxf(sqrtf(m2), 1e-15f);
    float u = fminf(xn, 1.0f - 1e-7f);
    float at = 0.5f * (log1pf(u) - log1pf(-u));
    float tt = tanhf(mn / xn * at);
    float sc = tt / mn;
    float rn = fmaxf(tt, 1e-15f);
    float pf = (rn > MAXNORM) ? (MAXNORM / rn) : 1.0f;
    float spf = sc * pf;

    float4 res[4];
#pragma unroll
    for (int j = 0; j < 4; ++j)
        res[j] = make_float4(mv[j].x * spf, mv[j].y * spf, mv[j].z * spf, mv[j].w * spf);

    float x2r = 0.0f, y2 = 0.0f, xy = 0.0f;
#pragma unroll
    for (int j = 0; j < 4; ++j) {
        x2r += dot4(res[j], res[j]);
        y2 += dot4(bv[j], bv[j]);
        xy += dot4(res[j], bv[j]);
    }
    x2r = warpSum(x2r); y2 = warpSum(y2); xy = warpSum(xy);

    float ca = 1.0f + 2.0f * xy + y2, cb = 1.0f - x2r;
    float den = fmaxf(1.0f + 2.0f * xy + x2r * y2, 1e-15f);
    float inv = 1.0f / den;
    float4 o[4];
    float o2 = 0.0f;
#pragma unroll
    for (int j = 0; j < 4; ++j) {
        o[j] = make_float4((ca * res[j].x + cb * bv[j].x) * inv,
                           (ca * res[j].y + cb * bv[j].y) * inv,
                           (ca * res[j].z + cb * bv[j].z) * inv,
                           (ca * res[j].w + cb * bv[j].w) * inv);
        o2 += dot4(o[j], o[j]);
    }
    o2 = warpSum(o2);
    float on = fmaxf(sqrtf(o2), 1e-15f);
    float pf2 = (on > MAXNORM) ? (MAXNORM / on) : 1.0f;
#pragma unroll
    for (int j = 0; j < 4; ++j) {
        o[j].x *= pf2; o[j].y *= pf2; o[j].z *= pf2; o[j].w *= pf2;
    }

    if (out) {
        float4* op = (float4*)(out + r * EDIM);
#pragma unroll
        for (int j = 0; j < 4; ++j) op[lane + 32 * j] = o[j];
    }
    if (ohi) {
#pragma unroll
        for (int j = 0; j < 4; ++j) {
            unsigned hp0 = packh2(o[j].x, o[j].y);
            unsigned hp1 = packh2(o[j].z, o[j].w);
            *(uint2*)(ohi + r * EDIM + (lane + 32 * j) * 4) = make_uint2(hp0, hp1);
        }
    }
    if (hn) {
        int bb = (int)(r / SEQ), s = (int)(r % SEQ);
#pragma unroll
        for (int j = 0; j < 4; ++j) {
            float hs = dot4(o[j], o[j]);
#pragma unroll
            for (int off = 8; off >= 1; off >>= 1)
                hs += __shfl_xor_sync(0xffffffffu, hs, off, 16);
            if ((lane & 15) == 0) {
                int head = (lane >> 4) + 2 * j;
                hn[((long)bb * NH + head) * SEQ + s] = fminf(hs, 1.0f - 1e-5f);
            }
        }
    }
}
// q and k fused (blockIdx.y selects)
__global__ __launch_bounds__(128) void mobius_qk(const float* __restrict__ x,
                                                 const float* __restrict__ qkv,
                                                 const float* __restrict__ bq,
                                                 const float* __restrict__ bk,
                                                 float* __restrict__ qn,
                                                 float* __restrict__ kn,
                                                 __half* __restrict__ qhb,
                                                 __half* __restrict__ khb) {
    int sel = blockIdx.y;
    mobius_core(x, qkv + sel * EDIM, 3 * EDIM, sel ? bk : bq,
                nullptr, sel ? kn : qn, sel ? khb : qhb);
}
__global__ __launch_bounds__(128) void mobius_one(const float* __restrict__ x,
                                                  const float* __restrict__ mx, long mxs,
                                                  const float* __restrict__ bias,
                                                  float* __restrict__ out,
                                                  __half* __restrict__ ohi) {
    mobius_core(x, mx, mxs, bias, out, nullptr, ohi);
}

// ---------------- flash hyperbolic attention v7 ----------------
// fp16 Q/K/V/P; Q fragments cached in registers; score loop restructured
// (one k-norm load per column, branchless clamp via fmax).
#define AP 72
#define KVU (64 * AP)
#define BUF2 (2 * KVU)
#define ASMB7 ((128 * AP + 2 * BUF2) * 2 + (128 + 2 * 64) * 4)
#define SC3 (-0.25503343f)        // -0.125 * log2(e) * sqrt(2)

__global__ void __launch_bounds__(256, 2) attn7(const __half* __restrict__ qh,
                                                const __half* __restrict__ kh,
                                                const __half* __restrict__ vh,
                                                const float* __restrict__ qn,
                                                const float* __restrict__ kn,
                                                float* __restrict__ o) {
    extern __shared__ __half hsm[];
    __half* Qs = hsm;
    __half* bufs[2] = { hsm + 128 * AP, hsm + 128 * AP + BUF2 };
    float* qns = (float*)(hsm + 128 * AP + 2 * BUF2);
    float* kns = qns + 128;

    const int tid = threadIdx.x, lane = tid & 31, w = tid >> 5;
    const int bh = blockIdx.y, b = bh >> 3, h = bh & 7;
    const int q0 = blockIdx.x * 128;
    const long qrow0 = (long)b * SEQ + q0;

#pragma unroll
    for (int it = 0; it < 4; ++it) {
        int slot = tid + it * 256;
        int r = slot >> 3, c8 = (slot & 7) * 8;
        *(uint4*)&Qs[r * AP + c8] = *(const uint4*)&qh[(qrow0 + r) * EDIM + h * DH + c8];
    }
    if (tid < 128) qns[tid] = qn[(long)bh * SEQ + q0 + tid];

    {
        const long krow0 = (long)b * SEQ;
#pragma unroll
        for (int it = 0; it < 2; ++it) {
            int slot = tid + it * 256;
            int r = slot >> 3, c8 = (slot & 7) * 8;
            long g = (krow0 + r) * EDIM + h * DH + c8;
            cpa16(&bufs[0][r * AP + c8], kh + g);
            cpa16(&bufs[0][KVU + r * AP + c8], vh + g);
        }
        if (tid < 16) cpa16(&kns[tid * 4], kn + (long)bh * SEQ + tid * 4);
        asm volatile("cp.async.commit_group;");
    }
    __syncthreads();

    // Q fragments cached in registers for the whole kernel
    unsigned qf[4][4];
#pragma unroll
    for (int cs = 0; cs < 4; ++cs)
        ldmA(qf[cs], Qs + (w * 16) * AP + cs * 16, AP);

    const float qv0 = qns[w * 16 + (lane >> 2)];
    const float qv1 = qns[w * 16 + (lane >> 2) + 8];
    const float oq0 = 1.0f - qv0, oq1 = 1.0f - qv1;
    const float oq0p = oq0 + 1e-5f, oq1p = oq1 + 1e-5f;

    float O[8][4] = {};
    float ls0 = 0.0f, ls1 = 0.0f;

    for (int t = 0; t < 32; ++t) {
        const int cur = t & 1;
        if (t + 1 < 32) {
            const long krow0 = (long)b * SEQ + (t + 1) * 64;
            __half* nb = bufs[1 - cur];
#pragma unroll
            for (int it = 0; it < 2; ++it) {
                int slot = tid + it * 256;
                int r = slot >> 3, c8 = (slot & 7) * 8;
                long g = (krow0 + r) * EDIM + h * DH + c8;
                cpa16(&nb[r * AP + c8], kh + g);
                cpa16(&nb[KVU + r * AP + c8], vh + g);
            }
            if (tid < 16) cpa16(&kns[(1 - cur) * 64 + tid * 4],
                                kn + (long)bh * SEQ + (t + 1) * 64 + tid * 4);
            asm volatile("cp.async.commit_group;");
            asm volatile("cp.async.wait_group 1;");
        } else {
            asm volatile("cp.async.wait_group 0;");
        }
        __syncthreads();

        const __half* Kt = bufs[cur];
        const __half* Vt = bufs[cur] + KVU;
        const float* knt = kns + cur * 64;

        // S = Q K^T (fp16, K=64), Q from registers
        float c[8][4] = {};
#pragma unroll
        for (int cs = 0; cs < 4; ++cs) {
#pragma unroll
            for (int np = 0; np < 4; ++np) {
                unsigned bb[4];
                ldmB2(bb, Kt + (np * 16) * AP + cs * 16, AP);
                mmaf16(c[2 * np], qf[cs], bb[0], bb[1]);
                mmaf16(c[2 * np + 1], qf[cs], bb[2], bb[3]);
            }
        }

        // score: s = SC3*uu*rsqrt(uu*dn); uu clamped via fmax (equiv to SEL form)
#pragma unroll
        for (int nt = 0; nt < 8; ++nt) {
#pragma unroll
            for (int j = 0; j < 2; ++j) {
                int col = nt * 8 + 2 * (lane & 3) + j;
                float kv = knt[col];
                float uu0 = fmaf(-qv0, kv, c[nt][j]);
                float dn0 = fmaf(-oq0, kv, oq0p);
                uu0 = fmaxf(uu0, 5e-6f * dn0);
                float p0 = ex2f((SC3 * uu0) * __frsqrt_rn(uu0 * dn0));
                c[nt][j] = p0; ls0 += p0;
                float uu1 = fmaf(-qv1, kv, c[nt][j + 2]);
                float dn1 = fmaf(-oq1, kv, oq1p);
                uu1 = fmaxf(uu1, 5e-6f * dn1);
                float p1 = ex2f((SC3 * uu1) * __frsqrt_rn(uu1 * dn1));
                c[nt][j + 2] = p1; ls1 += p1;
            }
        }

        // O += P V (fp16 single pass)
#pragma unroll
        for (int s = 0; s < 4; ++s) {
            unsigned AH[4];
#pragma unroll
            for (int half = 0; half < 2; ++half) {
                int t_ = 2 * s + half;
                AH[2 * half]     = packh2(c[t_][0], c[t_][1]);
                AH[2 * half + 1] = packh2(c[t_][2], c[t_][3]);
            }
#pragma unroll
            for (int np = 0; np < 4; ++np) {
                unsigned bh_[4];
                ldmBt(bh_, Vt + (s * 16) * AP + np * 16, AP);
                mmaf16(O[2 * np],     AH, bh_[0], bh_[1]);
                mmaf16(O[2 * np + 1], AH, bh_[2], bh_[3]);
            }
        }
        __syncthreads();
    }

    ls0 += __shfl_xor_sync(0xffffffffu, ls0, 1);
    ls0 += __shfl_xor_sync(0xffffffffu, ls0, 2);
    ls1 += __shfl_xor_sync(0xffffffffu, ls1, 1);
    ls1 += __shfl_xor_sync(0xffffffffu, ls1, 2);
    float il0 = 1.0f / ls0, il1 = 1.0f / ls1;

    int r0 = q0 + w * 16 + (lane >> 2);
    float* ob = o + ((long)b * SEQ + r0) * EDIM + h * DH;
#pragma unroll
    for (int nt = 0; nt < 8; ++nt) {
        int cc = nt * 8 + 2 * (lane & 3);
        *(float2*)(ob + cc) = make_float2(O[nt][0] * il0, O[nt][1] * il0);
        *(float2*)(ob + 8L * EDIM + cc) = make_float2(O[nt][2] * il1, O[nt][3] * il1);
    }
}

// ---------------- launch ----------------
extern "C" void kernel_launch(void* const* d_in, const int* in_sizes, int n_in,
                              void* d_out, int out_size) {
    const float* x  = (const float*)d_in[0];
    const float* Wq = (const float*)d_in[1];
    const float* bq = (const float*)d_in[2];
    const float* Wk = (const float*)d_in[3];
    const float* bk = (const float*)d_in[4];
    const float* Wv = (const float*)d_in[5];
    const float* bv = (const float*)d_in[6];
    const float* Wo = (const float*)d_in[7];
    const float* bo = (const float*)d_in[8];
    float* out = (float*)d_out;

    float *qkv, *st, *ao, *qn, *kn;
    __half *xcat, *wcat, *qhb, *khb, *vhb;
    cudaGetSymbolAddress((void**)&qkv, g_qkv);
    cudaGetSymbolAddress((void**)&st, g_st);
    cudaGetSymbolAddress((void**)&ao, g_ao);
    cudaGetSymbolAddress((void**)&qn, g_qn);
    cudaGetSymbolAddress((void**)&kn, g_kn);
    cudaGetSymbolAddress((void**)&xcat, g_xcat);
    cudaGetSymbolAddress((void**)&wcat, g_wcat);
    cudaGetSymbolAddress((void**)&qhb, g_qh);
    cudaGetSymbolAddress((void**)&khb, g_kh);
    cudaGetSymbolAddress((void**)&vhb, g_vh);

    cudaFuncSetAttribute(attn7, cudaFuncAttributeMaxDynamicSharedMemorySize, ASMB7);

    const long n2w = (long)EDIM * EDIM / 2;
    const long n2x = (long)ROWS * EDIM / 2;
    const long WSTR = (long)EDIM * KC2;

    dim3 gw((unsigned)((n2w + 255) / 256), 4);
    split_w<<<gw, 256>>>(Wq, Wk, Wv, Wo, wcat, n2w);
    split_x<<<(unsigned)((n2x + 255) / 256), 256>>>(x, xcat, n2x);

    dim3 gq(3 * EDIM / 128, ROWS / 128);   // (12, 64)
    gemm_f16<<<gq, 256>>>(xcat, wcat, qkv, ROWS, 3 * EDIM, KC2);

    dim3 gm(ROWS / 4, 2);
    mobius_qk<<<gm, 128>>>(x, qkv, bq, bk, qn, kn, qhb, khb);
    mobius_one<<<ROWS / 4, 128>>>(x, qkv + 2 * EDIM, 3 * EDIM, bv, nullptr, vhb);

    dim3 ag(SEQ / 128, BH);                // (16, 32)
    attn7<<<ag, 256, ASMB7>>>(qhb, khb, vhb, qn, kn, ao);

    split_x<<<(unsigned)((n2x + 255) / 256), 256>>>(ao, xcat, n2x);
    dim3 go(EDIM / 128, ROWS / 128);       // (4, 64)
    gemm_f16<<<go, 256>>>(xcat, wcat + 3 * WSTR, st, ROWS, EDIM, KC2);
    mobius_one<<<ROWS / 4, 128>>>(ao, st, EDIM, bo, out, nullptr);
}

// round 17
// speedup vs baseline: 1.8655x; 1.0265x over previous
#include <cuda_runtime.h>
#include <cuda_fp16.h>
#include <math.h>

#define EDIM 512
#define BDIM 4
#define SEQ  2048
#define NH   8
#define DH   64
#define ROWS (BDIM*SEQ)
#define BH   (BDIM*NH)
#define KC2  1024                 // fp16 2-term split-K
#define MAXNORM (1.0f - 4e-3f)

// ---------------- scratch ----------------
__device__ float g_qkv[(long)ROWS*3*EDIM];
__device__ float g_st[ROWS*EDIM];
__device__ float g_ao[ROWS*EDIM];
__device__ __half g_xcat[(long)ROWS*KC2];
__device__ __half g_wcat[4L*EDIM*KC2];
__device__ __half g_qh[ROWS*EDIM];
__device__ __half g_kh[ROWS*EDIM];
__device__ __half g_vh[ROWS*EDIM];
__device__ float g_qn[BH*SEQ];
__device__ float g_kn[BH*SEQ];

// ---------------- mma helpers ----------------
__device__ __forceinline__ void ldmA(unsigned r[4], const void* p0v, int pitch) {
    const __half* p0 = (const __half*)p0v;
    int l = threadIdx.x & 31;
    unsigned a = (unsigned)__cvta_generic_to_shared(p0 + (l & 15) * pitch + ((l >> 4) << 3));
    asm volatile("ldmatrix.sync.aligned.m8n8.x4.shared.b16 {%0,%1,%2,%3}, [%4];"
                 : "=r"(r[0]), "=r"(r[1]), "=r"(r[2]), "=r"(r[3]) : "r"(a));
}
__device__ __forceinline__ void ldmB2(unsigned r[4], const void* p0v, int pitch) {
    const __half* p0 = (const __half*)p0v;
    int l = threadIdx.x & 31;
    unsigned a = (unsigned)__cvta_generic_to_shared(p0 + ((l & 7) + ((l >> 4) << 3)) * pitch + (l & 8));
    asm volatile("ldmatrix.sync.aligned.m8n8.x4.shared.b16 {%0,%1,%2,%3}, [%4];"
                 : "=r"(r[0]), "=r"(r[1]), "=r"(r[2]), "=r"(r[3]) : "r"(a));
}
__device__ __forceinline__ void ldmBt(unsigned r[4], const void* p0v, int pitch) {
    const __half* p0 = (const __half*)p0v;
    int l = threadIdx.x & 31;
    unsigned a = (unsigned)__cvta_generic_to_shared(
        p0 + ((l & 7) + ((l >> 3) & 1) * 8) * pitch + ((l >> 4) << 3));
    asm volatile("ldmatrix.sync.aligned.m8n8.x4.trans.shared.b16 {%0,%1,%2,%3}, [%4];"
                 : "=r"(r[0]), "=r"(r[1]), "=r"(r[2]), "=r"(r[3]) : "r"(a));
}
__device__ __forceinline__ void mmaf16(float c[4], const unsigned a[4], unsigned b0, unsigned b1) {
    asm volatile("mma.sync.aligned.m16n8k16.row.col.f32.f16.f16.f32 "
                 "{%0,%1,%2,%3},{%4,%5,%6,%7},{%8,%9},{%0,%1,%2,%3};"
                 : "+f"(c[0]), "+f"(c[1]), "+f"(c[2]), "+f"(c[3])
                 : "r"(a[0]), "r"(a[1]), "r"(a[2]), "r"(a[3]), "r"(b0), "r"(b1));
}
__device__ __forceinline__ unsigned packh2(float lo, float hi) {
    __half2 h = __floats2half2_rn(lo, hi);
    return *(unsigned*)&h;
}
__device__ __forceinline__ unsigned ex2x2(unsigned a) {
    unsigned r;
    asm("ex2.approx.f16x2 %0, %1;" : "=r"(r) : "r"(a));
    return r;
}
__device__ __forceinline__ void cpa16(void* s, const void* g) {
    unsigned a = (unsigned)__cvta_generic_to_shared(s);
    asm volatile("cp.async.cg.shared.global [%0], [%1], 16;" :: "r"(a), "l"(g));
}

// ---------------- fp16 splits: x -> [hi|lo], W -> [hi|hi] ----------------
__device__ __forceinline__ void split_f16(const float* __restrict__ src,
                                          __half* __restrict__ dst, long i, int dup) {
    long e = i * 2;
    long r = e >> 9; int c = (int)(e & 511);
    float v0 = src[e], v1 = src[e + 1];
    __half h0 = __float2half_rn(v0), h1 = __float2half_rn(v1);
    __half* p = dst + r * KC2 + c;
    p[0] = h0; p[1] = h1;
    if (dup) { p[512] = h0; p[513] = h1; }
    else {
        p[512] = __float2half_rn(v0 - __half2float(h0));
        p[513] = __float2half_rn(v1 - __half2float(h1));
    }
}
__global__ __launch_bounds__(256) void split_x(const float* __restrict__ src,
                                               __half* __restrict__ dst, long n2) {
    long i = (long)blockIdx.x * blockDim.x + threadIdx.x;
    if (i >= n2) return;
    split_f16(src, dst, i, 0);
}
__global__ __launch_bounds__(256) void split_w(const float* __restrict__ w0,
                                               const float* __restrict__ w1,
                                               const float* __restrict__ w2,
                                               const float* __restrict__ w3,
                                               __half* __restrict__ dst, long n2) {
    long i = (long)blockIdx.x * blockDim.x + threadIdx.x;
    if (i >= n2) return;
    const float* srcs[4] = {w0, w1, w2, w3};
    split_f16(srcs[blockIdx.y], dst + (long)blockIdx.y * EDIM * KC2, i, 1);
}

// ---------------- fp16 NT GEMM, cp.async 2-stage: C fp32 = A[M,K] @ B[N,K]^T ----
__global__ __launch_bounds__(256) void gemm_f16(const __half* __restrict__ A,
                                                const __half* __restrict__ B,
                                                float* __restrict__ C,
                                                int M, int N, int K) {
    __shared__ __align__(16) __half As[2][128][40];
    __shared__ __align__(16) __half Bs[2][128][40];
    const int tid = threadIdx.x, lane = tid & 31, wid = tid >> 5;
    const int wm = wid & 3, wn = wid >> 2;
    const int bm = blockIdx.y * 128, bn = blockIdx.x * 128;

#pragma unroll
    for (int i = 0; i < 2; ++i) {
        int slot = tid + i * 256;
        int row = slot >> 2, ch = (slot & 3) * 8;
        cpa16(&As[0][row][ch], &A[(long)(bm + row) * K + ch]);
        cpa16(&Bs[0][row][ch], &B[(long)(bn + row) * K + ch]);
    }
    asm volatile("cp.async.commit_group;");

    const int T = K / 32;
    float acc[2][8][4] = {};
    for (int t = 0; t < T; ++t) {
        const int cur = t & 1;
        if (t + 1 < T) {
            const int kt = (t + 1) * 32;
#pragma unroll
            for (int i = 0; i < 2; ++i) {
                int slot = tid + i * 256;
                int row = slot >> 2, ch = (slot & 3) * 8;
                cpa16(&As[1 - cur][row][ch], &A[(long)(bm + row) * K + kt + ch]);
                cpa16(&Bs[1 - cur][row][ch], &B[(long)(bn + row) * K + kt + ch]);
            }
            asm volatile("cp.async.commit_group;");
            asm volatile("cp.async.wait_group 1;");
        } else {
            asm volatile("cp.async.wait_group 0;");
        }
        __syncthreads();
#pragma unroll
        for (int c = 0; c < 2; ++c) {
            unsigned a0[4], a1[4];
            ldmA(a0, &As[cur][wm * 32][c * 16], 40);
            ldmA(a1, &As[cur][wm * 32 + 16][c * 16], 40);
#pragma unroll
            for (int np = 0; np < 4; ++np) {
                unsigned b[4];
                ldmB2(b, &Bs[cur][wn * 64 + np * 16][c * 16], 40);
                mmaf16(acc[0][2 * np], a0, b[0], b[1]);
                mmaf16(acc[0][2 * np + 1], a0, b[2], b[3]);
                mmaf16(acc[1][2 * np], a1, b[0], b[1]);
                mmaf16(acc[1][2 * np + 1], a1, b[2], b[3]);
            }
        }
        __syncthreads();
    }
#pragma unroll
    for (int mt = 0; mt < 2; ++mt) {
        int r0 = bm + wm * 32 + mt * 16 + (lane >> 2);
#pragma unroll
        for (int nt = 0; nt < 8; ++nt) {
            int cc = bn + wn * 64 + nt * 8 + 2 * (lane & 3);
            *(float2*)&C[(long)r0 * N + cc] = make_float2(acc[mt][nt][0], acc[mt][nt][1]);
            *(float2*)&C[(long)(r0 + 8) * N + cc] = make_float2(acc[mt][nt][2], acc[mt][nt][3]);
        }
    }
}

// ---------------- warp-per-row Mobius transform core ----------------
__device__ __forceinline__ float dot4(float4 a, float4 b) {
    return a.x * b.x + a.y * b.y + a.z * b.z + a.w * b.w;
}
__device__ __forceinline__ float warpSum(float v) {
#pragma unroll
    for (int o = 16; o > 0; o >>= 1) v += __shfl_xor_sync(0xffffffffu, v, o);
    return v;
}
__device__ void mobius_core(const float* __restrict__ x,
                            const float* __restrict__ mx, long mxs,
                            const float* __restrict__ bias,
                            float* __restrict__ out,
                            float* __restrict__ hn,
                            __half* __restrict__ ohi) {
    const int lane = threadIdx.x & 31, w = threadIdx.x >> 5;
    const long r = blockIdx.x * 4 + w;
    const float4* xp = (const float4*)(x + r * EDIM);
    const float4* mp = (const float4*)(mx + r * mxs);
    const float4* bp = (const float4*)bias;

    float4 xv[4], mv[4], bv[4];
#pragma unroll
    for (int j = 0; j < 4; ++j) {
        xv[j] = xp[lane + 32 * j];
        mv[j] = mp[lane + 32 * j];
        bv[j] = bp[lane + 32 * j];
    }
    float x2 = 0.0f, m2 = 0.0f;
#pragma unroll
    for (int j = 0; j < 4; ++j) { x2 += dot4(xv[j], xv[j]); m2 += dot4(mv[j], mv[j]); }
    x2 = warpSum(x2); m2 = warpSum(m2);

    float xn = fmaxf(sqrtf(x2), 1e-15f);
    float mn = fmaxf(sqrtf(m2), 1e-15f);
    float u = fminf(xn, 1.0f - 1e-7f);
    float at = 0.5f * (log1pf(u) - log1pf(-u));
    float tt = tanhf(mn / xn * at);
    float sc = tt / mn;
    float rn = fmaxf(tt, 1e-15f);
    float pf = (rn > MAXNORM) ? (MAXNORM / rn) : 1.0f;
    float spf = sc * pf;

    float4 res[4];
#pragma unroll
    for (int j = 0; j < 4; ++j)
        res[j] = make_float4(mv[j].x * spf, mv[j].y * spf, mv[j].z * spf, mv[j].w * spf);

    float x2r = 0.0f, y2 = 0.0f, xy = 0.0f;
#pragma unroll
    for (int j = 0; j < 4; ++j) {
        x2r += dot4(res[j], res[j]);
        y2 += dot4(bv[j], bv[j]);
        xy += dot4(res[j], bv[j]);
    }
    x2r = warpSum(x2r); y2 = warpSum(y2); xy = warpSum(xy);

    float ca = 1.0f + 2.0f * xy + y2, cb = 1.0f - x2r;
    float den = fmaxf(1.0f + 2.0f * xy + x2r * y2, 1e-15f);
    float inv = 1.0f / den;
    float4 o[4];
    float o2 = 0.0f;
#pragma unroll
    for (int j = 0; j < 4; ++j) {
        o[j] = make_float4((ca * res[j].x + cb * bv[j].x) * inv,
                           (ca * res[j].y + cb * bv[j].y) * inv,
                           (ca * res[j].z + cb * bv[j].z) * inv,
                           (ca * res[j].w + cb * bv[j].w) * inv);
        o2 += dot4(o[j], o[j]);
    }
    o2 = warpSum(o2);
    float on = fmaxf(sqrtf(o2), 1e-15f);
    float pf2 = (on > MAXNORM) ? (MAXNORM / on) : 1.0f;
#pragma unroll
    for (int j = 0; j < 4; ++j) {
        o[j].x *= pf2; o[j].y *= pf2; o[j].z *= pf2; o[j].w *= pf2;
    }

    if (out) {
        float4* op = (float4*)(out + r * EDIM);
#pragma unroll
        for (int j = 0; j < 4; ++j) op[lane + 32 * j] = o[j];
    }
    if (ohi) {
#pragma unroll
        for (int j = 0; j < 4; ++j) {
            unsigned hp0 = packh2(o[j].x, o[j].y);
            unsigned hp1 = packh2(o[j].z, o[j].w);
            *(uint2*)(ohi + r * EDIM + (lane + 32 * j) * 4) = make_uint2(hp0, hp1);
        }
    }
    if (hn) {
        int bb = (int)(r / SEQ), s = (int)(r % SEQ);
#pragma unroll
        for (int j = 0; j < 4; ++j) {
            float hs = dot4(o[j], o[j]);
#pragma unroll
            for (int off = 8; off >= 1; off >>= 1)
                hs += __shfl_xor_sync(0xffffffffu, hs, off, 16);
            if ((lane & 15) == 0) {
                int head = (lane >> 4) + 2 * j;
                hn[((long)bb * NH + head) * SEQ + s] = fminf(hs, 1.0f - 1e-5f);
            }
        }
    }
}
__global__ __launch_bounds__(128) void mobius_qk(const float* __restrict__ x,
                                                 const float* __restrict__ qkv,
                                                 const float* __restrict__ bq,
                                                 const float* __restrict__ bk,
                                                 float* __restrict__ qn,
                                                 float* __restrict__ kn,
                                                 __half* __restrict__ qhb,
                                                 __half* __restrict__ khb) {
    int sel = blockIdx.y;
    mobius_core(x, qkv + sel * EDIM, 3 * EDIM, sel ? bk : bq,
                nullptr, sel ? kn : qn, sel ? khb : qhb);
}
__global__ __launch_bounds__(128) void mobius_one(const float* __restrict__ x,
                                                  const float* __restrict__ mx, long mxs,
                                                  const float* __restrict__ bias,
                                                  float* __restrict__ out,
                                                  __half* __restrict__ ohi) {
    mobius_core(x, mx, mxs, bias, out, nullptr, ohi);
}

// ---------------- flash hyperbolic attention v8 ----------------
// fp16 Q/K/V/P, Q frags in regs, ex2.approx.f16x2 (one MUFU per P-pair),
// row sums via ones-column in V pad (col 64) + extra MMA, quad broadcast.
#define AP 72
#define KVU (64 * AP)
#define BUF2 (2 * KVU)
#define ASMB8 ((128 * AP + 2 * BUF2) * 2 + (128 + 2 * 64) * 4)
#define SC3 (-0.25503343f)        // -0.125 * log2(e) * sqrt(2)

__global__ void __launch_bounds__(256, 2) attn8(const __half* __restrict__ qh,
                                                const __half* __restrict__ kh,
                                                const __half* __restrict__ vh,
                                                const float* __restrict__ qn,
                                                const float* __restrict__ kn,
                                                float* __restrict__ o) {
    extern __shared__ __half hsm[];
    __half* Qs = hsm;
    __half* bufs[2] = { hsm + 128 * AP, hsm + 128 * AP + BUF2 };
    float* qns = (float*)(hsm + 128 * AP + 2 * BUF2);
    float* kns = qns + 128;

    const int tid = threadIdx.x, lane = tid & 31, w = tid >> 5;
    const int bh = blockIdx.y, b = bh >> 3, h = bh & 7;
    const int q0 = blockIdx.x * 128;
    const long qrow0 = (long)b * SEQ + q0;

#pragma unroll
    for (int it = 0; it < 4; ++it) {
        int slot = tid + it * 256;
        int r = slot >> 3, c8 = (slot & 7) * 8;
        *(uint4*)&Qs[r * AP + c8] = *(const uint4*)&qh[(qrow0 + r) * EDIM + h * DH + c8];
    }
    if (tid < 128) qns[tid] = qn[(long)bh * SEQ + q0 + tid];

    // ones-column (col 64 = 1.0, cols 65..71 = 0) in V pad of BOTH buffers.
    // cp.async only writes cols 0..63, so this persists all tiles.
    if (tid < 128) {
        int buf = tid >> 6, r = tid & 63;
        *(uint4*)&bufs[buf][KVU + r * AP + 64] = make_uint4(0x00003C00u, 0u, 0u, 0u);
    }

    {
        const long krow0 = (long)b * SEQ;
#pragma unroll
        for (int it = 0; it < 2; ++it) {
            int slot = tid + it * 256;
            int r = slot >> 3, c8 = (slot & 7) * 8;
            long g = (krow0 + r) * EDIM + h * DH + c8;
            cpa16(&bufs[0][r * AP + c8], kh + g);
            cpa16(&bufs[0][KVU + r * AP + c8], vh + g);
        }
        if (tid < 16) cpa16(&kns[tid * 4], kn + (long)bh * SEQ + tid * 4);
        asm volatile("cp.async.commit_group;");
    }
    __syncthreads();

    // Q fragments cached in registers for the whole kernel
    unsigned qf[4][4];
#pragma unroll
    for (int cs = 0; cs < 4; ++cs)
        ldmA(qf[cs], Qs + (w * 16) * AP + cs * 16, AP);

    const float qv0 = qns[w * 16 + (lane >> 2)];
    const float qv1 = qns[w * 16 + (lane >> 2) + 8];
    const float oq0 = 1.0f - qv0, oq1 = 1.0f - qv1;
    const float oq0p = oq0 + 1e-5f, oq1p = oq1 + 1e-5f;

    float O[8][4] = {};
    float Os[4] = {};          // ones-column accumulator (Σp in slots 0/2 of quad-lane 0)

    for (int t = 0; t < 32; ++t) {
        const int cur = t & 1;
        if (t + 1 < 32) {
            const long krow0 = (long)b * SEQ + (t + 1) * 64;
            __half* nb = bufs[1 - cur];
#pragma unroll
            for (int it = 0; it < 2; ++it) {
                int slot = tid + it * 256;
                int r = slot >> 3, c8 = (slot & 7) * 8;
                long g = (krow0 + r) * EDIM + h * DH + c8;
                cpa16(&nb[r * AP + c8], kh + g);
                cpa16(&nb[KVU + r * AP + c8], vh + g);
            }
            if (tid < 16) cpa16(&kns[(1 - cur) * 64 + tid * 4],
                                kn + (long)bh * SEQ + (t + 1) * 64 + tid * 4);
            asm volatile("cp.async.commit_group;");
            asm volatile("cp.async.wait_group 1;");
        } else {
            asm volatile("cp.async.wait_group 0;");
        }
        __syncthreads();

        const __half* Kt = bufs[cur];
        const __half* Vt = bufs[cur] + KVU;
        const float* knt = kns + cur * 64;

        // S = Q K^T (fp16, K=64), Q from registers
        float c[8][4] = {};
#pragma unroll
        for (int cs = 0; cs < 4; ++cs) {
#pragma unroll
            for (int np = 0; np < 4; ++np) {
                unsigned bb[4];
                ldmB2(bb, Kt + (np * 16) * AP + cs * 16, AP);
                mmaf16(c[2 * np], qf[cs], bb[0], bb[1]);
                mmaf16(c[2 * np + 1], qf[cs], bb[2], bb[3]);
            }
        }

        // scores -> packed fp16 P pairs via one ex2.f16x2 per pair
        unsigned ph0[8], ph1[8];
#pragma unroll
        for (int nt = 0; nt < 8; ++nt) {
            int col = nt * 8 + 2 * (lane & 3);
            float kv0 = knt[col], kv1 = knt[col + 1];
            float u00 = fmaf(-qv0, kv0, c[nt][0]);
            float d00 = fmaf(-oq0, kv0, oq0p);
            u00 = fmaxf(u00, 5e-6f * d00);
            float s00 = (SC3 * u00) * __frsqrt_rn(u00 * d00);
            float u01 = fmaf(-qv0, kv1, c[nt][1]);
            float d01 = fmaf(-oq0, kv1, oq0p);
            u01 = fmaxf(u01, 5e-6f * d01);
            float s01 = (SC3 * u01) * __frsqrt_rn(u01 * d01);
            ph0[nt] = ex2x2(packh2(s00, s01));
            float u10 = fmaf(-qv1, kv0, c[nt][2]);
            float d10 = fmaf(-oq1, kv0, oq1p);
            u10 = fmaxf(u10, 5e-6f * d10);
            float s10 = (SC3 * u10) * __frsqrt_rn(u10 * d10);
            float u11 = fmaf(-qv1, kv1, c[nt][3]);
            float d11 = fmaf(-oq1, kv1, oq1p);
            u11 = fmaxf(u11, 5e-6f * d11);
            float s11 = (SC3 * u11) * __frsqrt_rn(u11 * d11);
            ph1[nt] = ex2x2(packh2(s10, s11));
        }

        // O += P V (fp16); ones-column MMA accumulates row sums into Os
#pragma unroll
        for (int s = 0; s < 4; ++s) {
            unsigned AH[4] = { ph0[2 * s], ph1[2 * s], ph0[2 * s + 1], ph1[2 * s + 1] };
#pragma unroll
            for (int np = 0; np < 4; ++np) {
                unsigned bh_[4];
                ldmBt(bh_, Vt + (s * 16) * AP + np * 16, AP);
                mmaf16(O[2 * np],     AH, bh_[0], bh_[1]);
                mmaf16(O[2 * np + 1], AH, bh_[2], bh_[3]);
            }
            unsigned bs_[4];
            ldmBt(bs_, Vt + (s * 16) * AP + 64, AP);
            mmaf16(Os, AH, bs_[0], bs_[1]);
        }
        __syncthreads();
    }

    // row sums live in quad-lane 0's Os[0] (row r0) and Os[2] (row r0+8)
    float ls0 = __shfl_sync(0xffffffffu, Os[0], lane & 28);
    float ls1 = __shfl_sync(0xffffffffu, Os[2], lane & 28);
    float il0 = 1.0f / ls0, il1 = 1.0f / ls1;

    int r0 = q0 + w * 16 + (lane >> 2);
    float* ob = o + ((long)b * SEQ + r0) * EDIM + h * DH;
#pragma unroll
    for (int nt = 0; nt < 8; ++nt) {
        int cc = nt * 8 + 2 * (lane & 3);
        *(float2*)(ob + cc) = make_float2(O[nt][0] * il0, O[nt][1] * il0);
        *(float2*)(ob + 8L * EDIM + cc) = make_float2(O[nt][2] * il1, O[nt][3] * il1);
    }
}

// ---------------- launch ----------------
extern "C" void kernel_launch(void* const* d_in, const int* in_sizes, int n_in,
                              void* d_out, int out_size) {
    const float* x  = (const float*)d_in[0];
    const float* Wq = (const float*)d_in[1];
    const float* bq = (const float*)d_in[2];
    const float* Wk = (const float*)d_in[3];
    const float* bk = (const float*)d_in[4];
    const float* Wv = (const float*)d_in[5];
    const float* bv = (const float*)d_in[6];
    const float* Wo = (const float*)d_in[7];
    const float* bo = (const float*)d_in[8];
    float* out = (float*)d_out;

    float *qkv, *st, *ao, *qn, *kn;
    __half *xcat, *wcat, *qhb, *khb, *vhb;
    cudaGetSymbolAddress((void**)&qkv, g_qkv);
    cudaGetSymbolAddress((void**)&st, g_st);
    cudaGetSymbolAddress((void**)&ao, g_ao);
    cudaGetSymbolAddress((void**)&qn, g_qn);
    cudaGetSymbolAddress((void**)&kn, g_kn);
    cudaGetSymbolAddress((void**)&xcat, g_xcat);
    cudaGetSymbolAddress((void**)&wcat, g_wcat);
    cudaGetSymbolAddress((void**)&qhb, g_qh);
    cudaGetSymbolAddress((void**)&khb, g_kh);
    cudaGetSymbolAddress((void**)&vhb, g_vh);

    cudaFuncSetAttribute(attn8, cudaFuncAttributeMaxDynamicSharedMemorySize, ASMB8);

    const long n2w = (long)EDIM * EDIM / 2;
    const long n2x = (long)ROWS * EDIM / 2;
    const long WSTR = (long)EDIM * KC2;

    dim3 gw((unsigned)((n2w + 255) / 256), 4);
    split_w<<<gw, 256>>>(Wq, Wk, Wv, Wo, wcat, n2w);
    split_x<<<(unsigned)((n2x + 255) / 256), 256>>>(x, xcat, n2x);

    dim3 gq(3 * EDIM / 128, ROWS / 128);   // (12, 64)
    gemm_f16<<<gq, 256>>>(xcat, wcat, qkv, ROWS, 3 * EDIM, KC2);

    dim3 gm(ROWS / 4, 2);
    mobius_qk<<<gm, 128>>>(x, qkv, bq, bk, qn, kn, qhb, khb);
    mobius_one<<<ROWS / 4, 128>>>(x, qkv + 2 * EDIM, 3 * EDIM, bv, nullptr, vhb);

    dim3 ag(SEQ / 128, BH);                // (16, 32)
    attn8<<<ag, 256, ASMB8>>>(qhb, khb, vhb, qn, kn, ao);

    split_x<<<(unsigned)((n2x + 255) / 256), 256>>>(ao, xcat, n2x);
    dim3 go(EDIM / 128, ROWS / 128);       // (4, 64)
    gemm_f16<<<go, 256>>>(xcat, wcat + 3 * WSTR, st, ROWS, EDIM, KC2);
    mobius_one<<<ROWS / 4, 128>>>(ao, st, EDIM, bo, out, nullptr);
}